// round 14
// baseline (speedup 1.0000x reference)
#include <cuda_runtime.h>
#include <cuda_bf16.h>
#include <math.h>
#include <stdint.h>

// ---------------- problem constants ----------------
#define Bsz 64
#define Hd  256
#define Dd  768
#define NRn 100000
#define ERn 400000
#define NCn 100000
#define ECn 300000
#define Gn  512
#define Hd2 (Hd / 2)

// ---------------- device scratch ----------------
__device__ __nv_bfloat162 g_XWr[(size_t)NRn * Hd2];   // y = (X@Wf)*dinv
__device__ __nv_bfloat162 g_P1r[(size_t)NRn * Hd2];   // q = relu(P1)*dinv
__device__ __nv_bfloat162 g_XWc[(size_t)NCn * Hd2];
__device__ __nv_bfloat162 g_P1c[(size_t)NCn * Hd2];
__device__ float g_Wf_r[Dd * Hd];
__device__ float g_Wf_c[Dd * Hd];
__device__ __nv_bfloat16 g_WtHiR[Hd * Dd];
__device__ __nv_bfloat16 g_WtHiC[Hd * Dd];
__device__ float g_pooled_r[Bsz * Hd];
__device__ float g_pooledG[Gn * Hd];
__device__ float g_graphs[Gn * Hd];
__device__ float g_reps[Bsz * 5 * Hd];
__device__ float g_hmid[Bsz * Hd];
// CSR scratch
__device__ int g_cnt_r[NRn];
__device__ int g_cnt_c[NCn];
__device__ int g_rowoff_r[NRn + 1];
__device__ int g_rowoff_c[NCn + 1];
__device__ int g_es_r[ERn];      // src only
__device__ int g_es_c[ECn];
__device__ int g_bsum2[1024];    // [2][512]

// ---------------- CSR build (both graphs per launch) ----------------
__global__ void count2_kernel(const int* __restrict__ dstR, const int* __restrict__ dstC,
                              int* __restrict__ cntR, int* __restrict__ cntC) {
    int e = blockIdx.x * blockDim.x + threadIdx.x;
    if (e < ERn) atomicAdd(&cntR[dstR[e]], 1);
    if (e < ECn) atomicAdd(&cntC[dstC[e]], 1);
}

__global__ void scan_blocksum2_kernel(const int* __restrict__ cntR, const int* __restrict__ cntC,
                                      int* __restrict__ bsum2, int n) {
    __shared__ int sh[256];
    const int* cnt = blockIdx.y ? cntC : cntR;
    int* bsum = bsum2 + blockIdx.y * 512;
    int tid = threadIdx.x;
    int i = blockIdx.x * 256 + tid;
    sh[tid] = (i < n) ? cnt[i] : 0;
    __syncthreads();
    for (int off = 128; off > 0; off >>= 1) {
        if (tid < off) sh[tid] += sh[tid + off];
        __syncthreads();
    }
    if (tid == 0) bsum[blockIdx.x] = sh[0];
}

__global__ void scan_bsum2_kernel(int* __restrict__ bsum2, int* __restrict__ roR,
                                  int* __restrict__ roC, int nb, int n) {
    __shared__ int sh[512];
    int* bsum = bsum2 + blockIdx.y * 512;
    int* rowoff = blockIdx.y ? roC : roR;
    int tid = threadIdx.x;
    int v = (tid < nb) ? bsum[tid] : 0;
    sh[tid] = v;
    __syncthreads();
    for (int off = 1; off < 512; off <<= 1) {
        int t = (tid >= off) ? sh[tid - off] : 0;
        __syncthreads();
        sh[tid] += t;
        __syncthreads();
    }
    if (tid < nb) bsum[tid] = sh[tid] - v;
    if (tid == 511) rowoff[n] = sh[511];
}

__global__ void scan_final2_kernel(const int* __restrict__ cntR, const int* __restrict__ cntC,
                                   const int* __restrict__ bsum2,
                                   int* __restrict__ roR, int* __restrict__ roC, int n) {
    __shared__ int sh[256];
    const int* cnt = blockIdx.y ? cntC : cntR;
    const int* bsum = bsum2 + blockIdx.y * 512;
    int* rowoff = blockIdx.y ? roC : roR;
    int tid = threadIdx.x;
    int i = blockIdx.x * 256 + tid;
    int v = (i < n) ? cnt[i] : 0;
    sh[tid] = v;
    __syncthreads();
    for (int off = 1; off < 256; off <<= 1) {
        int t = (tid >= off) ? sh[tid - off] : 0;
        __syncthreads();
        sh[tid] += t;
        __syncthreads();
    }
    if (i < n) rowoff[i] = bsum[blockIdx.x] + sh[tid] - v;
}

__global__ void scatter2_kernel(
    const int* __restrict__ srcR, const int* __restrict__ dstR,
    const int* __restrict__ roR, int* __restrict__ curR, int* __restrict__ esR,
    const int* __restrict__ srcC, const int* __restrict__ dstC,
    const int* __restrict__ roC, int* __restrict__ curC, int* __restrict__ esC)
{
    int e = blockIdx.x * blockDim.x + threadIdx.x;
    if (blockIdx.y == 0) {
        if (e < ERn) {
            int d = dstR[e];
            int pos = roR[d] + atomicAdd(&curR[d], 1);
            esR[pos] = srcR[e];
        }
    } else {
        if (e < ECn) {
            int d = dstC[e];
            int pos = roC[d] + atomicAdd(&curC[d], 1);
            esC[pos] = srcC[e];
        }
    }
}

// ---------------- bf16 CSR gather (layer 1, weightless edges, 1 node/block) ----------------
__device__ __forceinline__ float2 bf2f(const __nv_bfloat162 v) { return __bfloat1622float2(v); }

// in = y (already *dinv). out = relu( di*(y[n] + sum y[s]) ) * di   (premultiplied q)
// di = rsqrt(deg+1) derived from rowoff span
__global__ __launch_bounds__(128) void gather1_kernel(
    const __nv_bfloat162* __restrict__ inR, __nv_bfloat162* __restrict__ outR,
    const int* __restrict__ roR, const int* __restrict__ esR,
    const __nv_bfloat162* __restrict__ inC, __nv_bfloat162* __restrict__ outC,
    const int* __restrict__ roC, const int* __restrict__ esC)
{
    int n = blockIdx.x;
    const __nv_bfloat162* in; __nv_bfloat162* out; const int* ro; const int* es;
    if (n < NRn) { in = inR; out = outR; ro = roR; es = esR; }
    else { n -= NRn; in = inC; out = outC; ro = roC; es = esC; }

    int j = threadIdx.x;
    int beg = __ldg(&ro[n]), end = __ldg(&ro[n + 1]);
    float di = rsqrtf((float)(end - beg + 1));
    float2 v = bf2f(in[(size_t)n * Hd2 + j]);
    float ax = v.x, ay = v.y;
    int e = beg;
    for (; e + 8 <= end; e += 8) {
        int s0 = __ldg(&es[e]);
        int s1 = __ldg(&es[e + 1]);
        int s2 = __ldg(&es[e + 2]);
        int s3 = __ldg(&es[e + 3]);
        int s4 = __ldg(&es[e + 4]);
        int s5 = __ldg(&es[e + 5]);
        int s6 = __ldg(&es[e + 6]);
        int s7 = __ldg(&es[e + 7]);
        float2 x0 = bf2f(in[(size_t)s0 * Hd2 + j]);
        float2 x1 = bf2f(in[(size_t)s1 * Hd2 + j]);
        float2 x2 = bf2f(in[(size_t)s2 * Hd2 + j]);
        float2 x3 = bf2f(in[(size_t)s3 * Hd2 + j]);
        float2 x4 = bf2f(in[(size_t)s4 * Hd2 + j]);
        float2 x5 = bf2f(in[(size_t)s5 * Hd2 + j]);
        float2 x6 = bf2f(in[(size_t)s6 * Hd2 + j]);
        float2 x7 = bf2f(in[(size_t)s7 * Hd2 + j]);
        ax += ((x0.x + x1.x) + (x2.x + x3.x)) + ((x4.x + x5.x) + (x6.x + x7.x));
        ay += ((x0.y + x1.y) + (x2.y + x3.y)) + ((x4.y + x5.y) + (x6.y + x7.y));
    }
    for (; e < end; e++) {
        int s0 = __ldg(&es[e]);
        float2 x0 = bf2f(in[(size_t)s0 * Hd2 + j]);
        ax += x0.x;
        ay += x0.y;
    }
    float px = ax * di, py = ay * di;                 // P1
    out[(size_t)n * Hd2 + j] =
        __floats2bfloat162_rn(fmaxf(px, 0.f) * di, fmaxf(py, 0.f) * di);  // q
}

// ---------------- layer 2 + segment-pool; input is premultiplied q ----------------
__global__ __launch_bounds__(128) void gather2_pool_kernel(
    const __nv_bfloat162* __restrict__ inR, const int* __restrict__ roR,
    const int* __restrict__ esR, const int* __restrict__ batchR, float* __restrict__ poolR,
    const __nv_bfloat162* __restrict__ inC, const int* __restrict__ roC,
    const int* __restrict__ esC, const int* __restrict__ batchC, float* __restrict__ poolC)
{
    int n = blockIdx.x;
    const __nv_bfloat162* in; const int* ro; const int* es;
    const int* batch; float* pool;
    if (n < NRn) { in = inR; ro = roR; es = esR; batch = batchR; pool = poolR; }
    else { n -= NRn; in = inC; ro = roC; es = esC; batch = batchC; pool = poolC; }

    int j = threadIdx.x;
    int beg = __ldg(&ro[n]), end = __ldg(&ro[n + 1]);
    float di = rsqrtf((float)(end - beg + 1));
    float2 v = bf2f(in[(size_t)n * Hd2 + j]);         // q[n] already relu*dinv
    float ax = v.x, ay = v.y;
    int e = beg;
    for (; e + 8 <= end; e += 8) {
        int s0 = __ldg(&es[e]);
        int s1 = __ldg(&es[e + 1]);
        int s2 = __ldg(&es[e + 2]);
        int s3 = __ldg(&es[e + 3]);
        int s4 = __ldg(&es[e + 4]);
        int s5 = __ldg(&es[e + 5]);
        int s6 = __ldg(&es[e + 6]);
        int s7 = __ldg(&es[e + 7]);
        float2 x0 = bf2f(in[(size_t)s0 * Hd2 + j]);
        float2 x1 = bf2f(in[(size_t)s1 * Hd2 + j]);
        float2 x2 = bf2f(in[(size_t)s2 * Hd2 + j]);
        float2 x3 = bf2f(in[(size_t)s3 * Hd2 + j]);
        float2 x4 = bf2f(in[(size_t)s4 * Hd2 + j]);
        float2 x5 = bf2f(in[(size_t)s5 * Hd2 + j]);
        float2 x6 = bf2f(in[(size_t)s6 * Hd2 + j]);
        float2 x7 = bf2f(in[(size_t)s7 * Hd2 + j]);
        ax += ((x0.x + x1.x) + (x2.x + x3.x)) + ((x4.x + x5.x) + (x6.x + x7.x));
        ay += ((x0.y + x1.y) + (x2.y + x3.y)) + ((x4.y + x5.y) + (x6.y + x7.y));
    }
    for (; e < end; e++) {
        int s0 = __ldg(&es[e]);
        float2 x0 = bf2f(in[(size_t)s0 * Hd2 + j]);
        ax += x0.x;
        ay += x0.y;
    }
    int b = __ldg(&batch[n]);
    float* p = &pool[(size_t)b * Hd + j * 2];
    atomicAdd(p + 0, ax * di);
    atomicAdd(p + 1, ay * di);
}

__device__ __forceinline__ int lower_bound_dev(const int* a, int n, int v) {
    int lo = 0, hi = n;
    while (lo < hi) { int mid = (lo + hi) >> 1; if (a[mid] < v) lo = mid + 1; else hi = mid; }
    return lo;
}

__global__ void pool_partial_kernel(const float* __restrict__ x, const int* __restrict__ seg,
                                    int n, float* __restrict__ acc, int chunks) {
    int b = blockIdx.x;
    int chunk = blockIdx.y;
    int start = lower_bound_dev(seg, n, b);
    int end   = lower_bound_dev(seg, n, b + 1);
    int len = end - start;
    if (len <= 0) return;
    int per = (len + chunks - 1) / chunks;
    int s0 = start + chunk * per;
    int s1 = s0 + per; if (s1 > end) s1 = end;
    if (s0 >= s1) return;
    int j = threadIdx.x;
    float a = 0.0f;
    for (int r = s0; r < s1; r++) a += x[(size_t)r * Hd + j];
    atomicAdd(&acc[b * Hd + j], a);
}

__global__ void pool_div_kernel(const float* __restrict__ acc, const int* __restrict__ seg,
                                int n, float* __restrict__ dst, int ld) {
    int b = blockIdx.x;
    int j = threadIdx.x;
    int cnt = lower_bound_dev(seg, n, b + 1) - lower_bound_dev(seg, n, b);
    float c = fmaxf((float)cnt, 1.0f);
    dst[(size_t)b * ld + j] = acc[b * Hd + j] / c;
}

// ---------------- transpose+bf16 of both fused weights ----------------
__global__ void convtrans2_kernel(const float* __restrict__ W0, __nv_bfloat16* __restrict__ o0,
                                  const float* __restrict__ W1, __nv_bfloat16* __restrict__ o1) {
    int i = blockIdx.x * blockDim.x + threadIdx.x;
    if (i >= Dd * Hd) return;
    const float* W = blockIdx.y ? W1 : W0;
    __nv_bfloat16* o = blockIdx.y ? o1 : o0;
    int k = i / Hd, n = i % Hd;
    o[(size_t)n * Dd + k] = __float2bfloat16(W[i]);
}

// ---------------- tensor-core GEMM: bf16, double-buffered, dual, cnt-scaled epilogue ----------------
__device__ __forceinline__ void ldsm_x4(uint32_t r[4], const void* p) {
    uint32_t a = (uint32_t)__cvta_generic_to_shared(p);
    asm volatile("ldmatrix.sync.aligned.m8n8.x4.shared.b16 {%0,%1,%2,%3}, [%4];"
                 : "=r"(r[0]), "=r"(r[1]), "=r"(r[2]), "=r"(r[3]) : "r"(a));
}

__device__ __forceinline__ void mma_bf16(float acc[4], uint32_t a0, uint32_t a1,
                                         uint32_t a2, uint32_t a3,
                                         uint32_t b0, uint32_t b1) {
    asm volatile(
        "mma.sync.aligned.m16n8k16.row.col.f32.bf16.bf16.f32 "
        "{%0,%1,%2,%3},{%4,%5,%6,%7},{%8,%9},{%0,%1,%2,%3};"
        : "+f"(acc[0]), "+f"(acc[1]), "+f"(acc[2]), "+f"(acc[3])
        : "r"(a0), "r"(a1), "r"(a2), "r"(a3), "r"(b0), "r"(b1));
}

#define LDS_STRIDE 40
#define NITER (Dd / 32)   // 24

__global__ __launch_bounds__(256) void gemm_bf16_kernel(
    const float* A0, const __nv_bfloat16* Bt0, __nv_bfloat162* C0, const int* cnt0,
    const float* A1, const __nv_bfloat16* Bt1, __nv_bfloat162* C1, const int* cnt1,
    int M)
{
    const float* A = blockIdx.z ? A1 : A0;
    const __nv_bfloat16* Bt = blockIdx.z ? Bt1 : Bt0;
    __nv_bfloat162* C = blockIdx.z ? C1 : C0;
    const int* cnt = blockIdx.z ? cnt1 : cnt0;

    __shared__ __nv_bfloat16 As[2][128][LDS_STRIDE];
    __shared__ __nv_bfloat16 Bs[2][128][LDS_STRIDE];

    int tid = threadIdx.x;
    int warp = tid >> 5, lane = tid & 31;
    int bRow = blockIdx.y * 128, bCol = blockIdx.x * 128;
    int wm = (warp >> 2) * 64;
    int wn = (warp & 3) * 32;

    float acc[4][4][4];
#pragma unroll
    for (int a = 0; a < 4; a++)
#pragma unroll
        for (int b = 0; b < 4; b++)
#pragma unroll
            for (int c = 0; c < 4; c++) acc[a][b][c] = 0.0f;

    float4 aR[4];
    float4 bR[2];
    const float4 z4 = make_float4(0.f, 0.f, 0.f, 0.f);

#define LOAD_AB(k0)                                                           \
    {                                                                         \
        _Pragma("unroll")                                                     \
        for (int l = 0; l < 4; l++) {                                         \
            int i = tid + l * 256;                                            \
            int r = i >> 3, c4 = (i & 7) * 4;                                 \
            int gr = bRow + r;                                                \
            aR[l] = (gr < M) ? *(const float4*)&A[(size_t)gr * Dd + (k0) + c4]\
                             : z4;                                            \
        }                                                                     \
        _Pragma("unroll")                                                     \
        for (int l = 0; l < 2; l++) {                                         \
            int i = tid + l * 256;                                            \
            int r = i >> 2, c8 = (i & 3) * 8;                                 \
            bR[l] = *(const float4*)&Bt[(size_t)(bCol + r) * Dd + (k0) + c8]; \
        }                                                                     \
    }

#define STORE_AB(st)                                                          \
    {                                                                         \
        _Pragma("unroll")                                                     \
        for (int l = 0; l < 2; l++) {                                         \
            int i = tid + l * 256;                                            \
            int r = i >> 2, c8 = (i & 3) * 8;                                 \
            *(float4*)&Bs[st][r][c8] = bR[l];                                 \
        }                                                                     \
        _Pragma("unroll")                                                     \
        for (int l = 0; l < 4; l++) {                                         \
            int i = tid + l * 256;                                            \
            int r = i >> 3, c4 = (i & 7) * 4;                                 \
            float f[4] = {aR[l].x, aR[l].y, aR[l].z, aR[l].w};                \
            *(__nv_bfloat162*)&As[st][r][c4] =                                \
                __floats2bfloat162_rn(f[0], f[1]);                            \
            *(__nv_bfloat162*)&As[st][r][c4 + 2] =                            \
                __floats2bfloat162_rn(f[2], f[3]);                            \
        }                                                                     \
    }

    LOAD_AB(0);
    STORE_AB(0);
    LOAD_AB(32);
    __syncthreads();

    int mt = lane >> 3, ri = lane & 7;
    for (int it = 0; it < NITER; it++) {
        int cur = it & 1, nxt = cur ^ 1;
        if (it < NITER - 1) {
            STORE_AB(nxt);
            if (it < NITER - 2) LOAD_AB((it + 2) * 32);
        }
#pragma unroll
        for (int ks = 0; ks < 2; ks++) {
            int colOff = ks * 16 + (mt >> 1) * 8;
            uint32_t aH[4][4], bH[2][4];
#pragma unroll
            for (int mi = 0; mi < 4; mi++) {
                int row = wm + mi * 16 + (mt & 1) * 8 + ri;
                ldsm_x4(aH[mi], &As[cur][row][colOff]);
            }
#pragma unroll
            for (int bj = 0; bj < 2; bj++) {
                int row = wn + bj * 16 + (mt & 1) * 8 + ri;
                ldsm_x4(bH[bj], &Bs[cur][row][colOff]);
            }
#pragma unroll
            for (int mi = 0; mi < 4; mi++)
#pragma unroll
                for (int nj = 0; nj < 4; nj++) {
                    int bj = nj >> 1, s = nj & 1;
                    mma_bf16(acc[mi][nj], aH[mi][0], aH[mi][1], aH[mi][2], aH[mi][3],
                             bH[bj][s], bH[bj][s + 2]);
                }
        }
        __syncthreads();
    }
#undef LOAD_AB
#undef STORE_AB

    // epilogue: scale each row by rsqrt(cnt[row]+1), store bf16x2
    int g = lane >> 2, t = lane & 3;
#pragma unroll
    for (int mi = 0; mi < 4; mi++) {
        int row0 = bRow + wm + mi * 16 + g;
        float d0 = (row0 < M) ? rsqrtf((float)(__ldg(&cnt[row0]) + 1)) : 0.f;
        float d1 = (row0 + 8 < M) ? rsqrtf((float)(__ldg(&cnt[row0 + 8]) + 1)) : 0.f;
#pragma unroll
        for (int nj = 0; nj < 4; nj++) {
            int colp = (bCol + wn + nj * 8 + t * 2) >> 1;
            if (row0 < M)
                C[(size_t)row0 * Hd2 + colp] =
                    __floats2bfloat162_rn(acc[mi][nj][0] * d0, acc[mi][nj][1] * d0);
            if (row0 + 8 < M)
                C[(size_t)(row0 + 8) * Hd2 + colp] =
                    __floats2bfloat162_rn(acc[mi][nj][2] * d1, acc[mi][nj][3] * d1);
        }
    }
}

// ---------------- small fp32 GEMM (single) ----------------
__global__ __launch_bounds__(256) void sgemm64_kernel(const float* __restrict__ A, int lda,
                                                      const float* __restrict__ Bm,
                                                      const float* __restrict__ bias,
                                                      float* __restrict__ C, int ldc,
                                                      int M, int N, int K, int doRelu) {
    const int BM = 64, BN = 64, BK = 16, TM = 4, TN = 4;
    __shared__ float As[BK][BM];
    __shared__ float Bs[BK][BN];
    const int tid = threadIdx.x;
    const int bRow = blockIdx.y * BM;
    const int bCol = blockIdx.x * BN;
    const int tx = tid % 16;
    const int ty = tid / 16;

    float acc[TM][TN];
#pragma unroll
    for (int i = 0; i < TM; i++)
#pragma unroll
        for (int j = 0; j < TN; j++) acc[i][j] = 0.0f;

    for (int k0 = 0; k0 < K; k0 += BK) {
        {
            int i = tid;
            int r = i >> 2;
            int c4 = (i & 3) << 2;
            int grow = bRow + r;
            float4 v = make_float4(0.f, 0.f, 0.f, 0.f);
            if (grow < M) v = *reinterpret_cast<const float4*>(&A[(size_t)grow * lda + k0 + c4]);
            As[c4 + 0][r] = v.x; As[c4 + 1][r] = v.y; As[c4 + 2][r] = v.z; As[c4 + 3][r] = v.w;
        }
        {
            int i = tid;
            int r = i >> 4;
            int c = (i & 15) << 2;
            float4 v = *reinterpret_cast<const float4*>(&Bm[(size_t)(k0 + r) * N + bCol + c]);
            *reinterpret_cast<float4*>(&Bs[r][c]) = v;
        }
        __syncthreads();

        float ar[TM], br[TN];
#pragma unroll
        for (int kk = 0; kk < BK; kk++) {
#pragma unroll
            for (int i = 0; i < TM; i++) ar[i] = As[kk][ty * TM + i];
#pragma unroll
            for (int j = 0; j < TN; j++) br[j] = Bs[kk][tx * TN + j];
#pragma unroll
            for (int i = 0; i < TM; i++)
#pragma unroll
                for (int j = 0; j < TN; j++) acc[i][j] += ar[i] * br[j];
        }
        __syncthreads();
    }

#pragma unroll
    for (int i = 0; i < TM; i++) {
        int grow = bRow + ty * TM + i;
        if (grow >= M) continue;
#pragma unroll
        for (int j = 0; j < TN; j++) {
            int gcol = bCol + tx * TN + j;
            float v = acc[i][j];
            if (bias) v += bias[gcol];
            if (doRelu) v = fmaxf(v, 0.0f);
            C[(size_t)grow * ldc + gcol] = v;
        }
    }
}

// ---------------- small fp32 GEMM, 3-way z-select ----------------
__global__ __launch_bounds__(256) void sgemm64_3_kernel(
    const float* A0, const float* A1, const float* A2, int lda,
    const float* B0, const float* B1, const float* B2,
    float* C0, float* C1, float* C2, int ldc, int M, int N, int K)
{
    const float* A = (blockIdx.z == 0) ? A0 : (blockIdx.z == 1) ? A1 : A2;
    const float* Bm = (blockIdx.z == 0) ? B0 : (blockIdx.z == 1) ? B1 : B2;
    float* C = (blockIdx.z == 0) ? C0 : (blockIdx.z == 1) ? C1 : C2;

    const int BM = 64, BN = 64, BK = 16, TM = 4, TN = 4;
    __shared__ float As[BK][BM];
    __shared__ float Bs[BK][BN];
    const int tid = threadIdx.x;
    const int bRow = blockIdx.y * BM;
    const int bCol = blockIdx.x * BN;
    const int tx = tid % 16;
    const int ty = tid / 16;

    float acc[TM][TN];
#pragma unroll
    for (int i = 0; i < TM; i++)
#pragma unroll
        for (int j = 0; j < TN; j++) acc[i][j] = 0.0f;

    for (int k0 = 0; k0 < K; k0 += BK) {
        {
            int i = tid;
            int r = i >> 2;
            int c4 = (i & 3) << 2;
            int grow = bRow + r;
            float4 v = make_float4(0.f, 0.f, 0.f, 0.f);
            if (grow < M) v = *reinterpret_cast<const float4*>(&A[(size_t)grow * lda + k0 + c4]);
            As[c4 + 0][r] = v.x; As[c4 + 1][r] = v.y; As[c4 + 2][r] = v.z; As[c4 + 3][r] = v.w;
        }
        {
            int i = tid;
            int r = i >> 4;
            int c = (i & 15) << 2;
            float4 v = *reinterpret_cast<const float4*>(&Bm[(size_t)(k0 + r) * N + bCol + c]);
            *reinterpret_cast<float4*>(&Bs[r][c]) = v;
        }
        __syncthreads();

        float ar[TM], br[TN];
#pragma unroll
        for (int kk = 0; kk < BK; kk++) {
#pragma unroll
            for (int i = 0; i < TM; i++) ar[i] = As[kk][ty * TM + i];
#pragma unroll
            for (int j = 0; j < TN; j++) br[j] = Bs[kk][tx * TN + j];
#pragma unroll
            for (int i = 0; i < TM; i++)
#pragma unroll
                for (int j = 0; j < TN; j++) acc[i][j] += ar[i] * br[j];
        }
        __syncthreads();
    }

#pragma unroll
    for (int i = 0; i < TM; i++) {
        int grow = bRow + ty * TM + i;
        if (grow >= M) continue;
#pragma unroll
        for (int j = 0; j < TN; j++) {
            int gcol = bCol + tx * TN + j;
            C[(size_t)grow * ldc + gcol] = acc[i][j];
        }
    }
}

// ---------------- head ----------------
__global__ void head_kernel(const float* __restrict__ h, const float* __restrict__ W2,
                            const float* __restrict__ b2, const int* __restrict__ label,
                            float* __restrict__ out, int out_size) {
    __shared__ float preds[Bsz][2];
    int tid = threadIdx.x;
    if (tid < Bsz * 2) {
        int r = tid >> 1, c = tid & 1;
        float s = b2[c];
        for (int k = 0; k < Hd; k++) s += h[r * Hd + k] * W2[k * 2 + c];
        preds[r][c] = s;
    }
    __syncthreads();
    if (tid < Bsz * 2 && tid < out_size) out[tid] = preds[tid >> 1][tid & 1];
    if (tid == 0 && out_size >= Bsz * 2 + 1) {
        float loss = 0.0f;
        for (int r = 0; r < Bsz; r++) {
            float a = preds[r][0], b = preds[r][1];
            float m = fmaxf(a, b);
            float lse = m + logf(expf(a - m) + expf(b - m));
            int y = label[r];
            loss += lse - (y ? b : a);
        }
        out[Bsz * 2] = loss / (float)Bsz;
    }
}

// ---------------- launch (single stream) ----------------
extern "C" void kernel_launch(void* const* d_in, const int* in_sizes, int n_in,
                              void* d_out, int out_size) {
    const float* content  = (const float*)d_in[0];
    const float* video    = (const float*)d_in[1];
    const float* image    = (const float*)d_in[2];
    const float* repost_x = (const float*)d_in[3];
    const float* comment_x= (const float*)d_in[4];
    const float* W_text   = (const float*)d_in[5];
    const float* W_video  = (const float*)d_in[6];
    const float* W_image  = (const float*)d_in[7];
    const float* Wr1      = (const float*)d_in[8];
    const float* Wr2      = (const float*)d_in[9];
    const float* Wc1      = (const float*)d_in[10];
    const float* Wc2      = (const float*)d_in[11];
    const float* W1       = (const float*)d_in[12];
    const float* b1       = (const float*)d_in[13];
    const float* W2       = (const float*)d_in[14];
    const float* b2       = (const float*)d_in[15];
    const int* rei        = (const int*)d_in[16];
    const int* rbatch     = (const int*)d_in[17];
    const int* cei        = (const int*)d_in[18];
    const int* cbatch     = (const int*)d_in[19];
    const int* cgb        = (const int*)d_in[20];
    const int* label      = (const int*)d_in[21];
    float* out            = (float*)d_out;

    __nv_bfloat162 *pXWr, *pP1r, *pXWc, *pP1c;
    float *pWfr, *pWfc;
    float *pPoolR, *pPoolG, *pGraphs, *pReps, *pHmid;
    __nv_bfloat16 *pWtHiR, *pWtHiC;
    int *pCntR, *pCntC, *pRoR, *pRoC, *pBsum, *pEsR, *pEsC;
    cudaGetSymbolAddress((void**)&pXWr, g_XWr);
    cudaGetSymbolAddress((void**)&pP1r, g_P1r);
    cudaGetSymbolAddress((void**)&pXWc, g_XWc);
    cudaGetSymbolAddress((void**)&pP1c, g_P1c);
    cudaGetSymbolAddress((void**)&pWfr, g_Wf_r);
    cudaGetSymbolAddress((void**)&pWfc, g_Wf_c);
    cudaGetSymbolAddress((void**)&pWtHiR, g_WtHiR);
    cudaGetSymbolAddress((void**)&pWtHiC, g_WtHiC);
    cudaGetSymbolAddress((void**)&pPoolR, g_pooled_r);
    cudaGetSymbolAddress((void**)&pPoolG, g_pooledG);
    cudaGetSymbolAddress((void**)&pGraphs, g_graphs);
    cudaGetSymbolAddress((void**)&pReps, g_reps);
    cudaGetSymbolAddress((void**)&pHmid, g_hmid);
    cudaGetSymbolAddress((void**)&pCntR, g_cnt_r);
    cudaGetSymbolAddress((void**)&pCntC, g_cnt_c);
    cudaGetSymbolAddress((void**)&pRoR, g_rowoff_r);
    cudaGetSymbolAddress((void**)&pRoC, g_rowoff_c);
    cudaGetSymbolAddress((void**)&pEsR, g_es_r);
    cudaGetSymbolAddress((void**)&pEsC, g_es_c);
    cudaGetSymbolAddress((void**)&pBsum, g_bsum2);

    const int* r_src = rei;            const int* r_dst = rei + ERn;
    const int* c_src = cei;            const int* c_dst = cei + ECn;

    const int NB = (NRn + 255) / 256;  // 391

    // kernel launch order (memsets excluded from ncu index):
    // 0: count2   1: sgemm64_3   2: convtrans2   3: gemm_bf16 (ncu capture)
    cudaMemsetAsync(pCntR, 0, NRn * sizeof(int));
    cudaMemsetAsync(pCntC, 0, NCn * sizeof(int));
    count2_kernel<<<(ERn + 255) / 256, 256>>>(r_dst, c_dst, pCntR, pCntC);
    sgemm64_3_kernel<<<dim3(Hd / 64, Dd / 64, 2), 256>>>(
        W_text, W_text, W_text, Hd, Wr1, Wc1, Wc1, pWfr, pWfc, pWfc, Hd, Dd, Hd, Hd);
    convtrans2_kernel<<<dim3((Dd * Hd + 255) / 256, 2), 256>>>(pWfr, pWtHiR, pWfc, pWtHiC);
    gemm_bf16_kernel<<<dim3(2, (NRn + 127) / 128, 2), 256>>>(
        repost_x, pWtHiR, pXWr, pCntR, comment_x, pWtHiC, pXWc, pCntC, NRn);

    // ---- finish CSR (scans read cnt, then cnt re-zeroed as cursor) ----
    scan_blocksum2_kernel<<<dim3(NB, 2), 256>>>(pCntR, pCntC, pBsum, NRn);
    scan_bsum2_kernel<<<dim3(1, 2), 512>>>(pBsum, pRoR, pRoC, NB, NRn);
    scan_final2_kernel<<<dim3(NB, 2), 256>>>(pCntR, pCntC, pBsum, pRoR, pRoC, NRn);
    cudaMemsetAsync(pCntR, 0, NRn * sizeof(int));
    cudaMemsetAsync(pCntC, 0, NCn * sizeof(int));
    scatter2_kernel<<<dim3((ERn + 255) / 256, 2), 256>>>(
        r_src, r_dst, pRoR, pCntR, pEsR,
        c_src, c_dst, pRoC, pCntC, pEsC);

    // ---- layer-1 gather (both graphs, 1 node/block) ----
    gather1_kernel<<<NRn + NCn, 128>>>(pXWr, pP1r, pRoR, pEsR,
                                       pXWc, pP1c, pRoC, pEsC);

    // ---- layer-2 + pooling (1 node/block) ----
    cudaMemsetAsync(pPoolR, 0, (size_t)Bsz * Hd * sizeof(float));
    cudaMemsetAsync(pPoolG, 0, (size_t)Gn * Hd * sizeof(float));
    cudaMemsetAsync(pHmid, 0, (size_t)Bsz * Hd * sizeof(float));
    gather2_pool_kernel<<<NRn + NCn, 128>>>(pP1r, pRoR, pEsR, rbatch, pPoolR,
                                            pP1c, pRoC, pEsC, cbatch, pPoolG);
    pool_div_kernel<<<Bsz, Hd>>>(pPoolR, rbatch, NRn, pPoolR, Hd);
    pool_div_kernel<<<Gn, Hd>>>(pPoolG, cbatch, NCn, pPoolG, Hd);

    // graphs_reps = pooledG @ Wc2 ; second-level pool -> reps[:,2H:3H]
    sgemm64_kernel<<<dim3(Hd / 64, Gn / 64), 256>>>(pPoolG, Hd, Wc2, nullptr, pGraphs, Hd, Gn, Hd, Hd, 0);
    pool_partial_kernel<<<dim3(Bsz, 2), Hd>>>(pGraphs, cgb, Gn, pHmid, 2);
    pool_div_kernel<<<Bsz, Hd>>>(pHmid, cgb, Gn, pReps + 2 * Hd, 5 * Hd);

    // reps: content/video/image (one launch) + repost
    sgemm64_3_kernel<<<dim3(Hd / 64, 1, 3), 256>>>(
        content, video, image, Dd, W_text, W_video, W_image,
        pReps + 0 * Hd, pReps + 3 * Hd, pReps + 4 * Hd, 5 * Hd, Bsz, Hd, Dd);
    sgemm64_kernel<<<dim3(Hd / 64, 1), 256>>>(pPoolR, Hd, Wr2, nullptr, pReps + 1 * Hd, 5 * Hd, Bsz, Hd, Hd, 0);

    // MLP head
    sgemm64_kernel<<<dim3(Hd / 64, 1), 256>>>(pReps, 5 * Hd, W1, b1, pHmid, Hd, Bsz, Hd, 5 * Hd, 1);
    head_kernel<<<1, 128>>>(pHmid, W2, b2, label, out, out_size);
}

// round 15
// speedup vs baseline: 1.1622x; 1.1622x over previous
#include <cuda_runtime.h>
#include <cuda_bf16.h>
#include <math.h>
#include <stdint.h>

// ---------------- problem constants ----------------
#define Bsz 64
#define Hd  256
#define Dd  768
#define NRn 100000
#define ERn 400000
#define NCn 100000
#define ECn 300000
#define Gn  512
#define Hd2 (Hd / 2)

// ---------------- device scratch ----------------
__device__ __nv_bfloat162 g_XWr[(size_t)NRn * Hd2];   // y = (X@Wf)*dinv
__device__ __nv_bfloat162 g_P1r[(size_t)NRn * Hd2];   // q = relu(P1)*dinv
__device__ __nv_bfloat162 g_XWc[(size_t)NCn * Hd2];
__device__ __nv_bfloat162 g_P1c[(size_t)NCn * Hd2];
__device__ float g_dinv_r[NRn];
__device__ float g_dinv_c[NCn];
__device__ float g_Wf_r[Dd * Hd];
__device__ float g_Wf_c[Dd * Hd];
__device__ __nv_bfloat16 g_WtHiR[Hd * Dd];
__device__ __nv_bfloat16 g_WtHiC[Hd * Dd];
__device__ float g_pooled_r[Bsz * Hd];
__device__ float g_pooledG[Gn * Hd];
__device__ float g_graphs[Gn * Hd];
__device__ float g_reps[Bsz * 5 * Hd];
__device__ float g_hmid[Bsz * Hd];
// CSR scratch
__device__ int g_cnt_r[NRn];
__device__ int g_cnt_c[NCn];
__device__ int g_rowoff_r[NRn + 1];
__device__ int g_rowoff_c[NCn + 1];
__device__ int g_es_r[ERn];      // src only (weights folded into node rows)
__device__ int g_es_c[ECn];
__device__ int g_bsum2[1024];    // [2][512]

// ---------------- CSR build (both graphs per launch) ----------------
__global__ void count2_kernel(const int* __restrict__ dstR, const int* __restrict__ dstC,
                              int* __restrict__ cntR, int* __restrict__ cntC) {
    int e = blockIdx.x * blockDim.x + threadIdx.x;
    if (e < ERn) atomicAdd(&cntR[dstR[e]], 1);
    if (e < ECn) atomicAdd(&cntC[dstC[e]], 1);
}

__global__ void dinv2_kernel(const int* __restrict__ cntR, const int* __restrict__ cntC,
                             float* __restrict__ dR, float* __restrict__ dC) {
    int i = blockIdx.x * blockDim.x + threadIdx.x;
    if (i < NRn) dR[i] = rsqrtf((float)(cntR[i] + 1));
    if (i < NCn) dC[i] = rsqrtf((float)(cntC[i] + 1));
}

__global__ void scan_blocksum2_kernel(const int* __restrict__ cntR, const int* __restrict__ cntC,
                                      int* __restrict__ bsum2, int n) {
    __shared__ int sh[256];
    const int* cnt = blockIdx.y ? cntC : cntR;
    int* bsum = bsum2 + blockIdx.y * 512;
    int tid = threadIdx.x;
    int i = blockIdx.x * 256 + tid;
    sh[tid] = (i < n) ? cnt[i] : 0;
    __syncthreads();
    for (int off = 128; off > 0; off >>= 1) {
        if (tid < off) sh[tid] += sh[tid + off];
        __syncthreads();
    }
    if (tid == 0) bsum[blockIdx.x] = sh[0];
}

__global__ void scan_bsum2_kernel(int* __restrict__ bsum2, int* __restrict__ roR,
                                  int* __restrict__ roC, int nb, int n) {
    __shared__ int sh[512];
    int* bsum = bsum2 + blockIdx.y * 512;
    int* rowoff = blockIdx.y ? roC : roR;
    int tid = threadIdx.x;
    int v = (tid < nb) ? bsum[tid] : 0;
    sh[tid] = v;
    __syncthreads();
    for (int off = 1; off < 512; off <<= 1) {
        int t = (tid >= off) ? sh[tid - off] : 0;
        __syncthreads();
        sh[tid] += t;
        __syncthreads();
    }
    if (tid < nb) bsum[tid] = sh[tid] - v;
    if (tid == 511) rowoff[n] = sh[511];
}

__global__ void scan_final2_kernel(const int* __restrict__ cntR, const int* __restrict__ cntC,
                                   const int* __restrict__ bsum2,
                                   int* __restrict__ roR, int* __restrict__ roC, int n) {
    __shared__ int sh[256];
    const int* cnt = blockIdx.y ? cntC : cntR;
    const int* bsum = bsum2 + blockIdx.y * 512;
    int* rowoff = blockIdx.y ? roC : roR;
    int tid = threadIdx.x;
    int i = blockIdx.x * 256 + tid;
    int v = (i < n) ? cnt[i] : 0;
    sh[tid] = v;
    __syncthreads();
    for (int off = 1; off < 256; off <<= 1) {
        int t = (tid >= off) ? sh[tid - off] : 0;
        __syncthreads();
        sh[tid] += t;
        __syncthreads();
    }
    if (i < n) rowoff[i] = bsum[blockIdx.x] + sh[tid] - v;
}

__global__ void scatter2_kernel(
    const int* __restrict__ srcR, const int* __restrict__ dstR,
    const int* __restrict__ roR, int* __restrict__ curR, int* __restrict__ esR,
    const int* __restrict__ srcC, const int* __restrict__ dstC,
    const int* __restrict__ roC, int* __restrict__ curC, int* __restrict__ esC)
{
    int e = blockIdx.x * blockDim.x + threadIdx.x;
    if (blockIdx.y == 0) {
        if (e < ERn) {
            int d = dstR[e];
            int pos = roR[d] + atomicAdd(&curR[d], 1);
            esR[pos] = srcR[e];
        }
    } else {
        if (e < ECn) {
            int d = dstC[e];
            int pos = roC[d] + atomicAdd(&curC[d], 1);
            esC[pos] = srcC[e];
        }
    }
}

// ---------------- bf16 CSR gather (layer 1, weightless edges, 1 node/block) ----------------
__device__ __forceinline__ float2 bf2f(const __nv_bfloat162 v) { return __bfloat1622float2(v); }

// in = y (already *dinv). out = relu( di*(y[n] + sum y[s]) ) * di   (premultiplied q)
__global__ __launch_bounds__(128) void gather1_kernel(
    const __nv_bfloat162* __restrict__ inR, __nv_bfloat162* __restrict__ outR,
    const int* __restrict__ roR, const int* __restrict__ esR, const float* __restrict__ dR,
    const __nv_bfloat162* __restrict__ inC, __nv_bfloat162* __restrict__ outC,
    const int* __restrict__ roC, const int* __restrict__ esC, const float* __restrict__ dC)
{
    int n = blockIdx.x;
    const __nv_bfloat162* in; __nv_bfloat162* out; const int* ro; const int* es; const float* dv;
    if (n < NRn) { in = inR; out = outR; ro = roR; es = esR; dv = dR; }
    else { n -= NRn; in = inC; out = outC; ro = roC; es = esC; dv = dC; }

    int j = threadIdx.x;
    int beg = __ldg(&ro[n]), end = __ldg(&ro[n + 1]);
    float di = __ldg(&dv[n]);
    float2 v = bf2f(in[(size_t)n * Hd2 + j]);
    float ax = v.x, ay = v.y;
    int e = beg;
    for (; e + 8 <= end; e += 8) {
        int s0 = __ldg(&es[e]);
        int s1 = __ldg(&es[e + 1]);
        int s2 = __ldg(&es[e + 2]);
        int s3 = __ldg(&es[e + 3]);
        int s4 = __ldg(&es[e + 4]);
        int s5 = __ldg(&es[e + 5]);
        int s6 = __ldg(&es[e + 6]);
        int s7 = __ldg(&es[e + 7]);
        float2 x0 = bf2f(in[(size_t)s0 * Hd2 + j]);
        float2 x1 = bf2f(in[(size_t)s1 * Hd2 + j]);
        float2 x2 = bf2f(in[(size_t)s2 * Hd2 + j]);
        float2 x3 = bf2f(in[(size_t)s3 * Hd2 + j]);
        float2 x4 = bf2f(in[(size_t)s4 * Hd2 + j]);
        float2 x5 = bf2f(in[(size_t)s5 * Hd2 + j]);
        float2 x6 = bf2f(in[(size_t)s6 * Hd2 + j]);
        float2 x7 = bf2f(in[(size_t)s7 * Hd2 + j]);
        ax += ((x0.x + x1.x) + (x2.x + x3.x)) + ((x4.x + x5.x) + (x6.x + x7.x));
        ay += ((x0.y + x1.y) + (x2.y + x3.y)) + ((x4.y + x5.y) + (x6.y + x7.y));
    }
    for (; e < end; e++) {
        int s0 = __ldg(&es[e]);
        float2 x0 = bf2f(in[(size_t)s0 * Hd2 + j]);
        ax += x0.x;
        ay += x0.y;
    }
    float px = ax * di, py = ay * di;                 // P1
    out[(size_t)n * Hd2 + j] =
        __floats2bfloat162_rn(fmaxf(px, 0.f) * di, fmaxf(py, 0.f) * di);  // q
}

// ---------------- layer 2 + segment-pool; input is premultiplied q ----------------
__global__ __launch_bounds__(128) void gather2_pool_kernel(
    const __nv_bfloat162* __restrict__ inR, const int* __restrict__ roR,
    const int* __restrict__ esR, const float* __restrict__ dR,
    const int* __restrict__ batchR, float* __restrict__ poolR,
    const __nv_bfloat162* __restrict__ inC, const int* __restrict__ roC,
    const int* __restrict__ esC, const float* __restrict__ dC,
    const int* __restrict__ batchC, float* __restrict__ poolC)
{
    int n = blockIdx.x;
    const __nv_bfloat162* in; const int* ro; const int* es; const float* dv;
    const int* batch; float* pool;
    if (n < NRn) { in = inR; ro = roR; es = esR; dv = dR; batch = batchR; pool = poolR; }
    else { n -= NRn; in = inC; ro = roC; es = esC; dv = dC; batch = batchC; pool = poolC; }

    int j = threadIdx.x;
    int beg = __ldg(&ro[n]), end = __ldg(&ro[n + 1]);
    float di = __ldg(&dv[n]);
    float2 v = bf2f(in[(size_t)n * Hd2 + j]);         // q[n] already relu*dinv
    float ax = v.x, ay = v.y;
    int e = beg;
    for (; e + 8 <= end; e += 8) {
        int s0 = __ldg(&es[e]);
        int s1 = __ldg(&es[e + 1]);
        int s2 = __ldg(&es[e + 2]);
        int s3 = __ldg(&es[e + 3]);
        int s4 = __ldg(&es[e + 4]);
        int s5 = __ldg(&es[e + 5]);
        int s6 = __ldg(&es[e + 6]);
        int s7 = __ldg(&es[e + 7]);
        float2 x0 = bf2f(in[(size_t)s0 * Hd2 + j]);
        float2 x1 = bf2f(in[(size_t)s1 * Hd2 + j]);
        float2 x2 = bf2f(in[(size_t)s2 * Hd2 + j]);
        float2 x3 = bf2f(in[(size_t)s3 * Hd2 + j]);
        float2 x4 = bf2f(in[(size_t)s4 * Hd2 + j]);
        float2 x5 = bf2f(in[(size_t)s5 * Hd2 + j]);
        float2 x6 = bf2f(in[(size_t)s6 * Hd2 + j]);
        float2 x7 = bf2f(in[(size_t)s7 * Hd2 + j]);
        ax += ((x0.x + x1.x) + (x2.x + x3.x)) + ((x4.x + x5.x) + (x6.x + x7.x));
        ay += ((x0.y + x1.y) + (x2.y + x3.y)) + ((x4.y + x5.y) + (x6.y + x7.y));
    }
    for (; e < end; e++) {
        int s0 = __ldg(&es[e]);
        float2 x0 = bf2f(in[(size_t)s0 * Hd2 + j]);
        ax += x0.x;
        ay += x0.y;
    }
    int b = __ldg(&batch[n]);
    float* p = &pool[(size_t)b * Hd + j * 2];
    atomicAdd(p + 0, ax * di);
    atomicAdd(p + 1, ay * di);
}

__device__ __forceinline__ int lower_bound_dev(const int* a, int n, int v) {
    int lo = 0, hi = n;
    while (lo < hi) { int mid = (lo + hi) >> 1; if (a[mid] < v) lo = mid + 1; else hi = mid; }
    return lo;
}

__global__ void pool_partial_kernel(const float* __restrict__ x, const int* __restrict__ seg,
                                    int n, float* __restrict__ acc, int chunks) {
    int b = blockIdx.x;
    int chunk = blockIdx.y;
    int start = lower_bound_dev(seg, n, b);
    int end   = lower_bound_dev(seg, n, b + 1);
    int len = end - start;
    if (len <= 0) return;
    int per = (len + chunks - 1) / chunks;
    int s0 = start + chunk * per;
    int s1 = s0 + per; if (s1 > end) s1 = end;
    if (s0 >= s1) return;
    int j = threadIdx.x;
    float a = 0.0f;
    for (int r = s0; r < s1; r++) a += x[(size_t)r * Hd + j];
    atomicAdd(&acc[b * Hd + j], a);
}

__global__ void pool_div_kernel(const float* __restrict__ acc, const int* __restrict__ seg,
                                int n, float* __restrict__ dst, int ld) {
    int b = blockIdx.x;
    int j = threadIdx.x;
    int cnt = lower_bound_dev(seg, n, b + 1) - lower_bound_dev(seg, n, b);
    float c = fmaxf((float)cnt, 1.0f);
    dst[(size_t)b * ld + j] = acc[b * Hd + j] / c;
}

// ---------------- transpose+bf16 of both fused weights ----------------
__global__ void convtrans2_kernel(const float* __restrict__ W0, __nv_bfloat16* __restrict__ o0,
                                  const float* __restrict__ W1, __nv_bfloat16* __restrict__ o1) {
    int i = blockIdx.x * blockDim.x + threadIdx.x;
    if (i >= Dd * Hd) return;
    const float* W = blockIdx.y ? W1 : W0;
    __nv_bfloat16* o = blockIdx.y ? o1 : o0;
    int k = i / Hd, n = i % Hd;
    o[(size_t)n * Dd + k] = __float2bfloat16(W[i]);
}

// ---------------- tensor-core GEMM: bf16, double-buffered, single-graph, dinv epilogue ----------------
__device__ __forceinline__ void ldsm_x4(uint32_t r[4], const void* p) {
    uint32_t a = (uint32_t)__cvta_generic_to_shared(p);
    asm volatile("ldmatrix.sync.aligned.m8n8.x4.shared.b16 {%0,%1,%2,%3}, [%4];"
                 : "=r"(r[0]), "=r"(r[1]), "=r"(r[2]), "=r"(r[3]) : "r"(a));
}

__device__ __forceinline__ void mma_bf16(float acc[4], uint32_t a0, uint32_t a1,
                                         uint32_t a2, uint32_t a3,
                                         uint32_t b0, uint32_t b1) {
    asm volatile(
        "mma.sync.aligned.m16n8k16.row.col.f32.bf16.bf16.f32 "
        "{%0,%1,%2,%3},{%4,%5,%6,%7},{%8,%9},{%0,%1,%2,%3};"
        : "+f"(acc[0]), "+f"(acc[1]), "+f"(acc[2]), "+f"(acc[3])
        : "r"(a0), "r"(a1), "r"(a2), "r"(a3), "r"(b0), "r"(b1));
}

#define LDS_STRIDE 40
#define NITER (Dd / 32)   // 24

__global__ __launch_bounds__(256) void gemm_bf16_kernel(
    const float* __restrict__ A, const __nv_bfloat16* __restrict__ Bt,
    __nv_bfloat162* __restrict__ C, const float* __restrict__ dinv, int M)
{
    __shared__ __nv_bfloat16 As[2][128][LDS_STRIDE];
    __shared__ __nv_bfloat16 Bs[2][128][LDS_STRIDE];

    int tid = threadIdx.x;
    int warp = tid >> 5, lane = tid & 31;
    int bRow = blockIdx.y * 128, bCol = blockIdx.x * 128;
    int wm = (warp >> 2) * 64;
    int wn = (warp & 3) * 32;

    float acc[4][4][4];
#pragma unroll
    for (int a = 0; a < 4; a++)
#pragma unroll
        for (int b = 0; b < 4; b++)
#pragma unroll
            for (int c = 0; c < 4; c++) acc[a][b][c] = 0.0f;

    float4 aR[4];
    float4 bR[2];
    const float4 z4 = make_float4(0.f, 0.f, 0.f, 0.f);

#define LOAD_AB(k0)                                                           \
    {                                                                         \
        _Pragma("unroll")                                                     \
        for (int l = 0; l < 4; l++) {                                         \
            int i = tid + l * 256;                                            \
            int r = i >> 3, c4 = (i & 7) * 4;                                 \
            int gr = bRow + r;                                                \
            aR[l] = (gr < M) ? *(const float4*)&A[(size_t)gr * Dd + (k0) + c4]\
                             : z4;                                            \
        }                                                                     \
        _Pragma("unroll")                                                     \
        for (int l = 0; l < 2; l++) {                                         \
            int i = tid + l * 256;                                            \
            int r = i >> 2, c8 = (i & 3) * 8;                                 \
            bR[l] = *(const float4*)&Bt[(size_t)(bCol + r) * Dd + (k0) + c8]; \
        }                                                                     \
    }

#define STORE_AB(st)                                                          \
    {                                                                         \
        _Pragma("unroll")                                                     \
        for (int l = 0; l < 2; l++) {                                         \
            int i = tid + l * 256;                                            \
            int r = i >> 2, c8 = (i & 3) * 8;                                 \
            *(float4*)&Bs[st][r][c8] = bR[l];                                 \
        }                                                                     \
        _Pragma("unroll")                                                     \
        for (int l = 0; l < 4; l++) {                                         \
            int i = tid + l * 256;                                            \
            int r = i >> 3, c4 = (i & 7) * 4;                                 \
            float f[4] = {aR[l].x, aR[l].y, aR[l].z, aR[l].w};                \
            *(__nv_bfloat162*)&As[st][r][c4] =                                \
                __floats2bfloat162_rn(f[0], f[1]);                            \
            *(__nv_bfloat162*)&As[st][r][c4 + 2] =                            \
                __floats2bfloat162_rn(f[2], f[3]);                            \
        }                                                                     \
    }

    LOAD_AB(0);
    STORE_AB(0);
    LOAD_AB(32);
    __syncthreads();

    int mt = lane >> 3, ri = lane & 7;
    for (int it = 0; it < NITER; it++) {
        int cur = it & 1, nxt = cur ^ 1;
        if (it < NITER - 1) {
            STORE_AB(nxt);
            if (it < NITER - 2) LOAD_AB((it + 2) * 32);
        }
#pragma unroll
        for (int ks = 0; ks < 2; ks++) {
            int colOff = ks * 16 + (mt >> 1) * 8;
            uint32_t aH[4][4], bH[2][4];
#pragma unroll
            for (int mi = 0; mi < 4; mi++) {
                int row = wm + mi * 16 + (mt & 1) * 8 + ri;
                ldsm_x4(aH[mi], &As[cur][row][colOff]);
            }
#pragma unroll
            for (int bj = 0; bj < 2; bj++) {
                int row = wn + bj * 16 + (mt & 1) * 8 + ri;
                ldsm_x4(bH[bj], &Bs[cur][row][colOff]);
            }
#pragma unroll
            for (int mi = 0; mi < 4; mi++)
#pragma unroll
                for (int nj = 0; nj < 4; nj++) {
                    int bj = nj >> 1, s = nj & 1;
                    mma_bf16(acc[mi][nj], aH[mi][0], aH[mi][1], aH[mi][2], aH[mi][3],
                             bH[bj][s], bH[bj][s + 2]);
                }
        }
        __syncthreads();
    }
#undef LOAD_AB
#undef STORE_AB

    // epilogue: scale each row by dinv[row], store bf16x2
    int g = lane >> 2, t = lane & 3;
#pragma unroll
    for (int mi = 0; mi < 4; mi++) {
        int row0 = bRow + wm + mi * 16 + g;
        float d0 = (row0 < M) ? __ldg(&dinv[row0]) : 0.f;
        float d1 = (row0 + 8 < M) ? __ldg(&dinv[row0 + 8]) : 0.f;
#pragma unroll
        for (int nj = 0; nj < 4; nj++) {
            int colp = (bCol + wn + nj * 8 + t * 2) >> 1;
            if (row0 < M)
                C[(size_t)row0 * Hd2 + colp] =
                    __floats2bfloat162_rn(acc[mi][nj][0] * d0, acc[mi][nj][1] * d0);
            if (row0 + 8 < M)
                C[(size_t)(row0 + 8) * Hd2 + colp] =
                    __floats2bfloat162_rn(acc[mi][nj][2] * d1, acc[mi][nj][3] * d1);
        }
    }
}

// ---------------- small fp32 GEMM (single) ----------------
__global__ __launch_bounds__(256) void sgemm64_kernel(const float* __restrict__ A, int lda,
                                                      const float* __restrict__ Bm,
                                                      const float* __restrict__ bias,
                                                      float* __restrict__ C, int ldc,
                                                      int M, int N, int K, int doRelu) {
    const int BM = 64, BN = 64, BK = 16, TM = 4, TN = 4;
    __shared__ float As[BK][BM];
    __shared__ float Bs[BK][BN];
    const int tid = threadIdx.x;
    const int bRow = blockIdx.y * BM;
    const int bCol = blockIdx.x * BN;
    const int tx = tid % 16;
    const int ty = tid / 16;

    float acc[TM][TN];
#pragma unroll
    for (int i = 0; i < TM; i++)
#pragma unroll
        for (int j = 0; j < TN; j++) acc[i][j] = 0.0f;

    for (int k0 = 0; k0 < K; k0 += BK) {
        {
            int i = tid;
            int r = i >> 2;
            int c4 = (i & 3) << 2;
            int grow = bRow + r;
            float4 v = make_float4(0.f, 0.f, 0.f, 0.f);
            if (grow < M) v = *reinterpret_cast<const float4*>(&A[(size_t)grow * lda + k0 + c4]);
            As[c4 + 0][r] = v.x; As[c4 + 1][r] = v.y; As[c4 + 2][r] = v.z; As[c4 + 3][r] = v.w;
        }
        {
            int i = tid;
            int r = i >> 4;
            int c = (i & 15) << 2;
            float4 v = *reinterpret_cast<const float4*>(&Bm[(size_t)(k0 + r) * N + bCol + c]);
            *reinterpret_cast<float4*>(&Bs[r][c]) = v;
        }
        __syncthreads();

        float ar[TM], br[TN];
#pragma unroll
        for (int kk = 0; kk < BK; kk++) {
#pragma unroll
            for (int i = 0; i < TM; i++) ar[i] = As[kk][ty * TM + i];
#pragma unroll
            for (int j = 0; j < TN; j++) br[j] = Bs[kk][tx * TN + j];
#pragma unroll
            for (int i = 0; i < TM; i++)
#pragma unroll
                for (int j = 0; j < TN; j++) acc[i][j] += ar[i] * br[j];
        }
        __syncthreads();
    }

#pragma unroll
    for (int i = 0; i < TM; i++) {
        int grow = bRow + ty * TM + i;
        if (grow >= M) continue;
#pragma unroll
        for (int j = 0; j < TN; j++) {
            int gcol = bCol + tx * TN + j;
            float v = acc[i][j];
            if (bias) v += bias[gcol];
            if (doRelu) v = fmaxf(v, 0.0f);
            C[(size_t)grow * ldc + gcol] = v;
        }
    }
}

// ---------------- small fp32 GEMM, 3-way z-select ----------------
__global__ __launch_bounds__(256) void sgemm64_3_kernel(
    const float* A0, const float* A1, const float* A2, int lda,
    const float* B0, const float* B1, const float* B2,
    float* C0, float* C1, float* C2, int ldc, int M, int N, int K)
{
    const float* A = (blockIdx.z == 0) ? A0 : (blockIdx.z == 1) ? A1 : A2;
    const float* Bm = (blockIdx.z == 0) ? B0 : (blockIdx.z == 1) ? B1 : B2;
    float* C = (blockIdx.z == 0) ? C0 : (blockIdx.z == 1) ? C1 : C2;

    const int BM = 64, BN = 64, BK = 16, TM = 4, TN = 4;
    __shared__ float As[BK][BM];
    __shared__ float Bs[BK][BN];
    const int tid = threadIdx.x;
    const int bRow = blockIdx.y * BM;
    const int bCol = blockIdx.x * BN;
    const int tx = tid % 16;
    const int ty = tid / 16;

    float acc[TM][TN];
#pragma unroll
    for (int i = 0; i < TM; i++)
#pragma unroll
        for (int j = 0; j < TN; j++) acc[i][j] = 0.0f;

    for (int k0 = 0; k0 < K; k0 += BK) {
        {
            int i = tid;
            int r = i >> 2;
            int c4 = (i & 3) << 2;
            int grow = bRow + r;
            float4 v = make_float4(0.f, 0.f, 0.f, 0.f);
            if (grow < M) v = *reinterpret_cast<const float4*>(&A[(size_t)grow * lda + k0 + c4]);
            As[c4 + 0][r] = v.x; As[c4 + 1][r] = v.y; As[c4 + 2][r] = v.z; As[c4 + 3][r] = v.w;
        }
        {
            int i = tid;
            int r = i >> 4;
            int c = (i & 15) << 2;
            float4 v = *reinterpret_cast<const float4*>(&Bm[(size_t)(k0 + r) * N + bCol + c]);
            *reinterpret_cast<float4*>(&Bs[r][c]) = v;
        }
        __syncthreads();

        float ar[TM], br[TN];
#pragma unroll
        for (int kk = 0; kk < BK; kk++) {
#pragma unroll
            for (int i = 0; i < TM; i++) ar[i] = As[kk][ty * TM + i];
#pragma unroll
            for (int j = 0; j < TN; j++) br[j] = Bs[kk][tx * TN + j];
#pragma unroll
            for (int i = 0; i < TM; i++)
#pragma unroll
                for (int j = 0; j < TN; j++) acc[i][j] += ar[i] * br[j];
        }
        __syncthreads();
    }

#pragma unroll
    for (int i = 0; i < TM; i++) {
        int grow = bRow + ty * TM + i;
        if (grow >= M) continue;
#pragma unroll
        for (int j = 0; j < TN; j++) {
            int gcol = bCol + tx * TN + j;
            C[(size_t)grow * ldc + gcol] = acc[i][j];
        }
    }
}

// ---------------- head ----------------
__global__ void head_kernel(const float* __restrict__ h, const float* __restrict__ W2,
                            const float* __restrict__ b2, const int* __restrict__ label,
                            float* __restrict__ out, int out_size) {
    __shared__ float preds[Bsz][2];
    int tid = threadIdx.x;
    if (tid < Bsz * 2) {
        int r = tid >> 1, c = tid & 1;
        float s = b2[c];
        for (int k = 0; k < Hd; k++) s += h[r * Hd + k] * W2[k * 2 + c];
        preds[r][c] = s;
    }
    __syncthreads();
    if (tid < Bsz * 2 && tid < out_size) out[tid] = preds[tid >> 1][tid & 1];
    if (tid == 0 && out_size >= Bsz * 2 + 1) {
        float loss = 0.0f;
        for (int r = 0; r < Bsz; r++) {
            float a = preds[r][0], b = preds[r][1];
            float m = fmaxf(a, b);
            float lse = m + logf(expf(a - m) + expf(b - m));
            int y = label[r];
            loss += lse - (y ? b : a);
        }
        out[Bsz * 2] = loss / (float)Bsz;
    }
}

// ---------------- launch (single stream) ----------------
extern "C" void kernel_launch(void* const* d_in, const int* in_sizes, int n_in,
                              void* d_out, int out_size) {
    const float* content  = (const float*)d_in[0];
    const float* video    = (const float*)d_in[1];
    const float* image    = (const float*)d_in[2];
    const float* repost_x = (const float*)d_in[3];
    const float* comment_x= (const float*)d_in[4];
    const float* W_text   = (const float*)d_in[5];
    const float* W_video  = (const float*)d_in[6];
    const float* W_image  = (const float*)d_in[7];
    const float* Wr1      = (const float*)d_in[8];
    const float* Wr2      = (const float*)d_in[9];
    const float* Wc1      = (const float*)d_in[10];
    const float* Wc2      = (const float*)d_in[11];
    const float* W1       = (const float*)d_in[12];
    const float* b1       = (const float*)d_in[13];
    const float* W2       = (const float*)d_in[14];
    const float* b2       = (const float*)d_in[15];
    const int* rei        = (const int*)d_in[16];
    const int* rbatch     = (const int*)d_in[17];
    const int* cei        = (const int*)d_in[18];
    const int* cbatch     = (const int*)d_in[19];
    const int* cgb        = (const int*)d_in[20];
    const int* label      = (const int*)d_in[21];
    float* out            = (float*)d_out;

    __nv_bfloat162 *pXWr, *pP1r, *pXWc, *pP1c;
    float *pDr, *pDc, *pWfr, *pWfc;
    float *pPoolR, *pPoolG, *pGraphs, *pReps, *pHmid;
    __nv_bfloat16 *pWtHiR, *pWtHiC;
    int *pCntR, *pCntC, *pRoR, *pRoC, *pBsum, *pEsR, *pEsC;
    cudaGetSymbolAddress((void**)&pXWr, g_XWr);
    cudaGetSymbolAddress((void**)&pP1r, g_P1r);
    cudaGetSymbolAddress((void**)&pXWc, g_XWc);
    cudaGetSymbolAddress((void**)&pP1c, g_P1c);
    cudaGetSymbolAddress((void**)&pDr, g_dinv_r);
    cudaGetSymbolAddress((void**)&pDc, g_dinv_c);
    cudaGetSymbolAddress((void**)&pWfr, g_Wf_r);
    cudaGetSymbolAddress((void**)&pWfc, g_Wf_c);
    cudaGetSymbolAddress((void**)&pWtHiR, g_WtHiR);
    cudaGetSymbolAddress((void**)&pWtHiC, g_WtHiC);
    cudaGetSymbolAddress((void**)&pPoolR, g_pooled_r);
    cudaGetSymbolAddress((void**)&pPoolG, g_pooledG);
    cudaGetSymbolAddress((void**)&pGraphs, g_graphs);
    cudaGetSymbolAddress((void**)&pReps, g_reps);
    cudaGetSymbolAddress((void**)&pHmid, g_hmid);
    cudaGetSymbolAddress((void**)&pCntR, g_cnt_r);
    cudaGetSymbolAddress((void**)&pCntC, g_cnt_c);
    cudaGetSymbolAddress((void**)&pRoR, g_rowoff_r);
    cudaGetSymbolAddress((void**)&pRoC, g_rowoff_c);
    cudaGetSymbolAddress((void**)&pEsR, g_es_r);
    cudaGetSymbolAddress((void**)&pEsC, g_es_c);
    cudaGetSymbolAddress((void**)&pBsum, g_bsum2);

    const int* r_src = rei;            const int* r_dst = rei + ERn;
    const int* c_src = cei;            const int* c_dst = cei + ECn;

    const int NB = (NRn + 255) / 256;  // 391

    // ---- degrees first (dinv feeds the GEMM epilogue) ----
    cudaMemsetAsync(pCntR, 0, NRn * sizeof(int));
    cudaMemsetAsync(pCntC, 0, NCn * sizeof(int));
    count2_kernel<<<(ERn + 255) / 256, 256>>>(r_dst, c_dst, pCntR, pCntC);
    dinv2_kernel<<<NB, 256>>>(pCntR, pCntC, pDr, pDc);

    // ---- weight prep + two single-graph tensor-core GEMMs (writes y = XW*dinv) ----
    sgemm64_3_kernel<<<dim3(Hd / 64, Dd / 64, 2), 256>>>(
        W_text, W_text, W_text, Hd, Wr1, Wc1, Wc1, pWfr, pWfc, pWfc, Hd, Dd, Hd, Hd);
    convtrans2_kernel<<<dim3((Dd * Hd + 255) / 256, 2), 256>>>(pWfr, pWtHiR, pWfc, pWtHiC);
    gemm_bf16_kernel<<<dim3(2, (NRn + 127) / 128), 256>>>(repost_x, pWtHiR, pXWr, pDr, NRn);
    gemm_bf16_kernel<<<dim3(2, (NCn + 127) / 128), 256>>>(comment_x, pWtHiC, pXWc, pDc, NCn);

    // ---- finish CSR (scans + scatter; weightless payload) ----
    scan_blocksum2_kernel<<<dim3(NB, 2), 256>>>(pCntR, pCntC, pBsum, NRn);
    scan_bsum2_kernel<<<dim3(1, 2), 512>>>(pBsum, pRoR, pRoC, NB, NRn);
    scan_final2_kernel<<<dim3(NB, 2), 256>>>(pCntR, pCntC, pBsum, pRoR, pRoC, NRn);
    cudaMemsetAsync(pCntR, 0, NRn * sizeof(int));
    cudaMemsetAsync(pCntC, 0, NCn * sizeof(int));
    scatter2_kernel<<<dim3((ERn + 255) / 256, 2), 256>>>(
        r_src, r_dst, pRoR, pCntR, pEsR,
        c_src, c_dst, pRoC, pCntC, pEsC);

    // ---- layer-1 gather (both graphs, 1 node/block) ----
    gather1_kernel<<<NRn + NCn, 128>>>(pXWr, pP1r, pRoR, pEsR, pDr,
                                       pXWc, pP1c, pRoC, pEsC, pDc);

    // ---- layer-2 + pooling (1 node/block) ----
    cudaMemsetAsync(pPoolR, 0, (size_t)Bsz * Hd * sizeof(float));
    cudaMemsetAsync(pPoolG, 0, (size_t)Gn * Hd * sizeof(float));
    cudaMemsetAsync(pHmid, 0, (size_t)Bsz * Hd * sizeof(float));
    gather2_pool_kernel<<<NRn + NCn, 128>>>(pP1r, pRoR, pEsR, pDr, rbatch, pPoolR,
                                            pP1c, pRoC, pEsC, pDc, cbatch, pPoolG);
    pool_div_kernel<<<Bsz, Hd>>>(pPoolR, rbatch, NRn, pPoolR, Hd);
    pool_div_kernel<<<Gn, Hd>>>(pPoolG, cbatch, NCn, pPoolG, Hd);

    // graphs_reps = pooledG @ Wc2 ; second-level pool -> reps[:,2H:3H]
    sgemm64_kernel<<<dim3(Hd / 64, Gn / 64), 256>>>(pPoolG, Hd, Wc2, nullptr, pGraphs, Hd, Gn, Hd, Hd, 0);
    pool_partial_kernel<<<dim3(Bsz, 2), Hd>>>(pGraphs, cgb, Gn, pHmid, 2);
    pool_div_kernel<<<Bsz, Hd>>>(pHmid, cgb, Gn, pReps + 2 * Hd, 5 * Hd);

    // reps: content/video/image (one launch) + repost
    sgemm64_3_kernel<<<dim3(Hd / 64, 1, 3), 256>>>(
        content, video, image, Dd, W_text, W_video, W_image,
        pReps + 0 * Hd, pReps + 3 * Hd, pReps + 4 * Hd, 5 * Hd, Bsz, Hd, Dd);
    sgemm64_kernel<<<dim3(Hd / 64, 1), 256>>>(pPoolR, Hd, Wr2, nullptr, pReps + 1 * Hd, 5 * Hd, Bsz, Hd, Hd, 0);

    // MLP head
    sgemm64_kernel<<<dim3(Hd / 64, 1), 256>>>(pReps, 5 * Hd, W1, b1, pHmid, Hd, Bsz, Hd, 5 * Hd, 1);
    head_kernel<<<1, 128>>>(pHmid, W2, b2, label, out, out_size);
}

// round 17
// speedup vs baseline: 1.1954x; 1.0285x over previous
#include <cuda_runtime.h>
#include <cuda_bf16.h>
#include <math.h>
#include <stdint.h>

// ---------------- problem constants ----------------
#define Bsz 64
#define Hd  256
#define Dd  768
#define NRn 100000
#define ERn 400000
#define NCn 100000
#define ECn 300000
#define Gn  512
#define Hd2 (Hd / 2)

// ---------------- device scratch ----------------
__device__ __nv_bfloat162 g_XWr[(size_t)NRn * Hd2];   // y = (X@Wf)*dinv
__device__ __nv_bfloat162 g_P1r[(size_t)NRn * Hd2];   // q = relu(P1)*dinv
__device__ __nv_bfloat162 g_XWc[(size_t)NCn * Hd2];
__device__ __nv_bfloat162 g_P1c[(size_t)NCn * Hd2];
__device__ float g_dinv_r[NRn];
__device__ float g_dinv_c[NCn];
__device__ float g_Wf_r[Dd * Hd];
__device__ float g_Wf_c[Dd * Hd];
__device__ __nv_bfloat16 g_WtHiR[Hd * Dd];
__device__ __nv_bfloat16 g_WtHiC[Hd * Dd];
__device__ float g_pooled_r[Bsz * Hd];
__device__ float g_pooledG[Gn * Hd];
__device__ float g_graphs[Gn * Hd];
__device__ float g_reps[Bsz * 5 * Hd];
__device__ float g_hmid[Bsz * Hd];
// CSR scratch
__device__ int g_cnt_r[NRn];
__device__ int g_cnt_c[NCn];
__device__ int g_rowoff_r[NRn + 1];
__device__ int g_rowoff_c[NCn + 1];
__device__ int g_es_r[ERn];      // src only (weights folded into node rows)
__device__ int g_es_c[ECn];
__device__ int g_bsum2[1024];    // [2][512]

// ---------------- CSR build (both graphs per launch) ----------------
__global__ void count2_kernel(const int* __restrict__ dstR, const int* __restrict__ dstC,
                              int* __restrict__ cntR, int* __restrict__ cntC) {
    int e = blockIdx.x * blockDim.x + threadIdx.x;
    if (e < ERn) atomicAdd(&cntR[dstR[e]], 1);
    if (e < ECn) atomicAdd(&cntC[dstC[e]], 1);
}

__global__ void dinv2_kernel(const int* __restrict__ cntR, const int* __restrict__ cntC,
                             float* __restrict__ dR, float* __restrict__ dC) {
    int i = blockIdx.x * blockDim.x + threadIdx.x;
    if (i < NRn) dR[i] = rsqrtf((float)(cntR[i] + 1));
    if (i < NCn) dC[i] = rsqrtf((float)(cntC[i] + 1));
}

__global__ void scan_blocksum2_kernel(const int* __restrict__ cntR, const int* __restrict__ cntC,
                                      int* __restrict__ bsum2, int n) {
    __shared__ int sh[256];
    const int* cnt = blockIdx.y ? cntC : cntR;
    int* bsum = bsum2 + blockIdx.y * 512;
    int tid = threadIdx.x;
    int i = blockIdx.x * 256 + tid;
    sh[tid] = (i < n) ? cnt[i] : 0;
    __syncthreads();
    for (int off = 128; off > 0; off >>= 1) {
        if (tid < off) sh[tid] += sh[tid + off];
        __syncthreads();
    }
    if (tid == 0) bsum[blockIdx.x] = sh[0];
}

__global__ void scan_bsum2_kernel(int* __restrict__ bsum2, int* __restrict__ roR,
                                  int* __restrict__ roC, int nb, int n) {
    __shared__ int sh[512];
    int* bsum = bsum2 + blockIdx.y * 512;
    int* rowoff = blockIdx.y ? roC : roR;
    int tid = threadIdx.x;
    int v = (tid < nb) ? bsum[tid] : 0;
    sh[tid] = v;
    __syncthreads();
    for (int off = 1; off < 512; off <<= 1) {
        int t = (tid >= off) ? sh[tid - off] : 0;
        __syncthreads();
        sh[tid] += t;
        __syncthreads();
    }
    if (tid < nb) bsum[tid] = sh[tid] - v;
    if (tid == 511) rowoff[n] = sh[511];
}

__global__ void scan_final2_kernel(const int* __restrict__ cntR, const int* __restrict__ cntC,
                                   const int* __restrict__ bsum2,
                                   int* __restrict__ roR, int* __restrict__ roC, int n) {
    __shared__ int sh[256];
    const int* cnt = blockIdx.y ? cntC : cntR;
    const int* bsum = bsum2 + blockIdx.y * 512;
    int* rowoff = blockIdx.y ? roC : roR;
    int tid = threadIdx.x;
    int i = blockIdx.x * 256 + tid;
    int v = (i < n) ? cnt[i] : 0;
    sh[tid] = v;
    __syncthreads();
    for (int off = 1; off < 256; off <<= 1) {
        int t = (tid >= off) ? sh[tid - off] : 0;
        __syncthreads();
        sh[tid] += t;
        __syncthreads();
    }
    if (i < n) rowoff[i] = bsum[blockIdx.x] + sh[tid] - v;
}

__global__ void scatter2_kernel(
    const int* __restrict__ srcR, const int* __restrict__ dstR,
    const int* __restrict__ roR, int* __restrict__ curR, int* __restrict__ esR,
    const int* __restrict__ srcC, const int* __restrict__ dstC,
    const int* __restrict__ roC, int* __restrict__ curC, int* __restrict__ esC)
{
    int e = blockIdx.x * blockDim.x + threadIdx.x;
    if (blockIdx.y == 0) {
        if (e < ERn) {
            int d = dstR[e];
            int pos = roR[d] + atomicAdd(&curR[d], 1);
            esR[pos] = srcR[e];
        }
    } else {
        if (e < ECn) {
            int d = dstC[e];
            int pos = roC[d] + atomicAdd(&curC[d], 1);
            esC[pos] = srcC[e];
        }
    }
}

// ---------------- bf16 CSR gather (layer 1, weightless edges, 1 node/block) ----------------
__device__ __forceinline__ float2 bf2f(const __nv_bfloat162 v) { return __bfloat1622float2(v); }

// in = y (already *dinv). out = relu( di*(y[n] + sum y[s]) ) * di   (premultiplied q)
__global__ __launch_bounds__(128) void gather1_kernel(
    const __nv_bfloat162* __restrict__ inR, __nv_bfloat162* __restrict__ outR,
    const int* __restrict__ roR, const int* __restrict__ esR, const float* __restrict__ dR,
    const __nv_bfloat162* __restrict__ inC, __nv_bfloat162* __restrict__ outC,
    const int* __restrict__ roC, const int* __restrict__ esC, const float* __restrict__ dC)
{
    int n = blockIdx.x;
    const __nv_bfloat162* in; __nv_bfloat162* out; const int* ro; const int* es; const float* dv;
    if (n < NRn) { in = inR; out = outR; ro = roR; es = esR; dv = dR; }
    else { n -= NRn; in = inC; out = outC; ro = roC; es = esC; dv = dC; }

    int j = threadIdx.x;
    int beg = __ldg(&ro[n]), end = __ldg(&ro[n + 1]);
    float di = __ldg(&dv[n]);
    float2 v = bf2f(in[(size_t)n * Hd2 + j]);
    float ax = v.x, ay = v.y;
    int e = beg;
    for (; e + 8 <= end; e += 8) {
        int s0 = __ldg(&es[e]);
        int s1 = __ldg(&es[e + 1]);
        int s2 = __ldg(&es[e + 2]);
        int s3 = __ldg(&es[e + 3]);
        int s4 = __ldg(&es[e + 4]);
        int s5 = __ldg(&es[e + 5]);
        int s6 = __ldg(&es[e + 6]);
        int s7 = __ldg(&es[e + 7]);
        float2 x0 = bf2f(in[(size_t)s0 * Hd2 + j]);
        float2 x1 = bf2f(in[(size_t)s1 * Hd2 + j]);
        float2 x2 = bf2f(in[(size_t)s2 * Hd2 + j]);
        float2 x3 = bf2f(in[(size_t)s3 * Hd2 + j]);
        float2 x4 = bf2f(in[(size_t)s4 * Hd2 + j]);
        float2 x5 = bf2f(in[(size_t)s5 * Hd2 + j]);
        float2 x6 = bf2f(in[(size_t)s6 * Hd2 + j]);
        float2 x7 = bf2f(in[(size_t)s7 * Hd2 + j]);
        ax += ((x0.x + x1.x) + (x2.x + x3.x)) + ((x4.x + x5.x) + (x6.x + x7.x));
        ay += ((x0.y + x1.y) + (x2.y + x3.y)) + ((x4.y + x5.y) + (x6.y + x7.y));
    }
    for (; e < end; e++) {
        int s0 = __ldg(&es[e]);
        float2 x0 = bf2f(in[(size_t)s0 * Hd2 + j]);
        ax += x0.x;
        ay += x0.y;
    }
    float px = ax * di, py = ay * di;                 // P1
    out[(size_t)n * Hd2 + j] =
        __floats2bfloat162_rn(fmaxf(px, 0.f) * di, fmaxf(py, 0.f) * di);  // q
}

// ---------------- layer 2 + segment-pool; input is premultiplied q ----------------
__global__ __launch_bounds__(128) void gather2_pool_kernel(
    const __nv_bfloat162* __restrict__ inR, const int* __restrict__ roR,
    const int* __restrict__ esR, const float* __restrict__ dR,
    const int* __restrict__ batchR, float* __restrict__ poolR,
    const __nv_bfloat162* __restrict__ inC, const int* __restrict__ roC,
    const int* __restrict__ esC, const float* __restrict__ dC,
    const int* __restrict__ batchC, float* __restrict__ poolC)
{
    int n = blockIdx.x;
    const __nv_bfloat162* in; const int* ro; const int* es; const float* dv;
    const int* batch; float* pool;
    if (n < NRn) { in = inR; ro = roR; es = esR; dv = dR; batch = batchR; pool = poolR; }
    else { n -= NRn; in = inC; ro = roC; es = esC; dv = dC; batch = batchC; pool = poolC; }

    int j = threadIdx.x;
    int beg = __ldg(&ro[n]), end = __ldg(&ro[n + 1]);
    float di = __ldg(&dv[n]);
    float2 v = bf2f(in[(size_t)n * Hd2 + j]);         // q[n] already relu*dinv
    float ax = v.x, ay = v.y;
    int e = beg;
    for (; e + 8 <= end; e += 8) {
        int s0 = __ldg(&es[e]);
        int s1 = __ldg(&es[e + 1]);
        int s2 = __ldg(&es[e + 2]);
        int s3 = __ldg(&es[e + 3]);
        int s4 = __ldg(&es[e + 4]);
        int s5 = __ldg(&es[e + 5]);
        int s6 = __ldg(&es[e + 6]);
        int s7 = __ldg(&es[e + 7]);
        float2 x0 = bf2f(in[(size_t)s0 * Hd2 + j]);
        float2 x1 = bf2f(in[(size_t)s1 * Hd2 + j]);
        float2 x2 = bf2f(in[(size_t)s2 * Hd2 + j]);
        float2 x3 = bf2f(in[(size_t)s3 * Hd2 + j]);
        float2 x4 = bf2f(in[(size_t)s4 * Hd2 + j]);
        float2 x5 = bf2f(in[(size_t)s5 * Hd2 + j]);
        float2 x6 = bf2f(in[(size_t)s6 * Hd2 + j]);
        float2 x7 = bf2f(in[(size_t)s7 * Hd2 + j]);
        ax += ((x0.x + x1.x) + (x2.x + x3.x)) + ((x4.x + x5.x) + (x6.x + x7.x));
        ay += ((x0.y + x1.y) + (x2.y + x3.y)) + ((x4.y + x5.y) + (x6.y + x7.y));
    }
    for (; e < end; e++) {
        int s0 = __ldg(&es[e]);
        float2 x0 = bf2f(in[(size_t)s0 * Hd2 + j]);
        ax += x0.x;
        ay += x0.y;
    }
    int b = __ldg(&batch[n]);
    float* p = &pool[(size_t)b * Hd + j * 2];
    atomicAdd(p + 0, ax * di);
    atomicAdd(p + 1, ay * di);
}

__device__ __forceinline__ int lower_bound_dev(const int* a, int n, int v) {
    int lo = 0, hi = n;
    while (lo < hi) { int mid = (lo + hi) >> 1; if (a[mid] < v) lo = mid + 1; else hi = mid; }
    return lo;
}

// in-place mean-div for both pools in ONE launch: blocks [0,Gn) -> poolG, [Gn,Gn+Bsz) -> poolR
__global__ void pool_div2_kernel(float* __restrict__ accR, const int* __restrict__ segR,
                                 float* __restrict__ accG, const int* __restrict__ segG) {
    int b = blockIdx.x;
    int j = threadIdx.x;
    if (b < Gn) {
        int cnt = lower_bound_dev(segG, NCn, b + 1) - lower_bound_dev(segG, NCn, b);
        float c = fmaxf((float)cnt, 1.0f);
        accG[(size_t)b * Hd + j] /= c;
    } else {
        int bb = b - Gn;
        int cnt = lower_bound_dev(segR, NRn, bb + 1) - lower_bound_dev(segR, NRn, bb);
        float c = fmaxf((float)cnt, 1.0f);
        accR[(size_t)bb * Hd + j] /= c;
    }
}

// fused second-level pool: reps[:,2H:3H] = mean over cgb segments of graphs rows (direct write)
__global__ void pool_graphs_kernel(const float* __restrict__ graphs, const int* __restrict__ cgb,
                                   float* __restrict__ dst, int ld) {
    int b = blockIdx.x;   // 0..Bsz-1
    int j = threadIdx.x;  // 256
    int start = lower_bound_dev(cgb, Gn, b);
    int end   = lower_bound_dev(cgb, Gn, b + 1);
    float a = 0.0f;
    for (int r = start; r < end; r++) a += graphs[(size_t)r * Hd + j];
    float c = fmaxf((float)(end - start), 1.0f);
    dst[(size_t)b * ld + j] = a / c;
}

// ---------------- transpose+bf16 of both fused weights ----------------
__global__ void convtrans2_kernel(const float* __restrict__ W0, __nv_bfloat16* __restrict__ o0,
                                  const float* __restrict__ W1, __nv_bfloat16* __restrict__ o1) {
    int i = blockIdx.x * blockDim.x + threadIdx.x;
    if (i >= Dd * Hd) return;
    const float* W = blockIdx.y ? W1 : W0;
    __nv_bfloat16* o = blockIdx.y ? o1 : o0;
    int k = i / Hd, n = i % Hd;
    o[(size_t)n * Dd + k] = __float2bfloat16(W[i]);
}

// ---------------- tensor-core GEMM: bf16, double-buffered, dual, dinv epilogue ----------------
__device__ __forceinline__ void ldsm_x4(uint32_t r[4], const void* p) {
    uint32_t a = (uint32_t)__cvta_generic_to_shared(p);
    asm volatile("ldmatrix.sync.aligned.m8n8.x4.shared.b16 {%0,%1,%2,%3}, [%4];"
                 : "=r"(r[0]), "=r"(r[1]), "=r"(r[2]), "=r"(r[3]) : "r"(a));
}

__device__ __forceinline__ void mma_bf16(float acc[4], uint32_t a0, uint32_t a1,
                                         uint32_t a2, uint32_t a3,
                                         uint32_t b0, uint32_t b1) {
    asm volatile(
        "mma.sync.aligned.m16n8k16.row.col.f32.bf16.bf16.f32 "
        "{%0,%1,%2,%3},{%4,%5,%6,%7},{%8,%9},{%0,%1,%2,%3};"
        : "+f"(acc[0]), "+f"(acc[1]), "+f"(acc[2]), "+f"(acc[3])
        : "r"(a0), "r"(a1), "r"(a2), "r"(a3), "r"(b0), "r"(b1));
}

#define LDS_STRIDE 40
#define NITER (Dd / 32)   // 24

__global__ __launch_bounds__(256) void gemm_bf16_kernel(
    const float* A0, const __nv_bfloat16* Bt0, __nv_bfloat162* C0, const float* dinv0,
    const float* A1, const __nv_bfloat16* Bt1, __nv_bfloat162* C1, const float* dinv1,
    int M)
{
    const float* A = blockIdx.z ? A1 : A0;
    const __nv_bfloat16* Bt = blockIdx.z ? Bt1 : Bt0;
    __nv_bfloat162* C = blockIdx.z ? C1 : C0;
    const float* dinv = blockIdx.z ? dinv1 : dinv0;

    __shared__ __nv_bfloat16 As[2][128][LDS_STRIDE];
    __shared__ __nv_bfloat16 Bs[2][128][LDS_STRIDE];

    int tid = threadIdx.x;
    int warp = tid >> 5, lane = tid & 31;
    int bRow = blockIdx.y * 128, bCol = blockIdx.x * 128;
    int wm = (warp >> 2) * 64;
    int wn = (warp & 3) * 32;

    float acc[4][4][4];
#pragma unroll
    for (int a = 0; a < 4; a++)
#pragma unroll
        for (int b = 0; b < 4; b++)
#pragma unroll
            for (int c = 0; c < 4; c++) acc[a][b][c] = 0.0f;

    float4 aR[4];
    float4 bR[2];
    const float4 z4 = make_float4(0.f, 0.f, 0.f, 0.f);

#define LOAD_AB(k0)                                                           \
    {                                                                         \
        _Pragma("unroll")                                                     \
        for (int l = 0; l < 4; l++) {                                         \
            int i = tid + l * 256;                                            \
            int r = i >> 3, c4 = (i & 7) * 4;                                 \
            int gr = bRow + r;                                                \
            aR[l] = (gr < M) ? *(const float4*)&A[(size_t)gr * Dd + (k0) + c4]\
                             : z4;                                            \
        }                                                                     \
        _Pragma("unroll")                                                     \
        for (int l = 0; l < 2; l++) {                                         \
            int i = tid + l * 256;                                            \
            int r = i >> 2, c8 = (i & 3) * 8;                                 \
            bR[l] = *(const float4*)&Bt[(size_t)(bCol + r) * Dd + (k0) + c8]; \
        }                                                                     \
    }

#define STORE_AB(st)                                                          \
    {                                                                         \
        _Pragma("unroll")                                                     \
        for (int l = 0; l < 2; l++) {                                         \
            int i = tid + l * 256;                                            \
            int r = i >> 2, c8 = (i & 3) * 8;                                 \
            *(float4*)&Bs[st][r][c8] = bR[l];                                 \
        }                                                                     \
        _Pragma("unroll")                                                     \
        for (int l = 0; l < 4; l++) {                                         \
            int i = tid + l * 256;                                            \
            int r = i >> 3, c4 = (i & 7) * 4;                                 \
            float f[4] = {aR[l].x, aR[l].y, aR[l].z, aR[l].w};                \
            *(__nv_bfloat162*)&As[st][r][c4] =                                \
                __floats2bfloat162_rn(f[0], f[1]);                            \
            *(__nv_bfloat162*)&As[st][r][c4 + 2] =                            \
                __floats2bfloat162_rn(f[2], f[3]);                            \
        }                                                                     \
    }

    LOAD_AB(0);
    STORE_AB(0);
    LOAD_AB(32);
    __syncthreads();

    int mt = lane >> 3, ri = lane & 7;
    for (int it = 0; it < NITER; it++) {
        int cur = it & 1, nxt = cur ^ 1;
        if (it < NITER - 1) {
            STORE_AB(nxt);
            if (it < NITER - 2) LOAD_AB((it + 2) * 32);
        }
#pragma unroll
        for (int ks = 0; ks < 2; ks++) {
            int colOff = ks * 16 + (mt >> 1) * 8;
            uint32_t aH[4][4], bH[2][4];
#pragma unroll
            for (int mi = 0; mi < 4; mi++) {
                int row = wm + mi * 16 + (mt & 1) * 8 + ri;
                ldsm_x4(aH[mi], &As[cur][row][colOff]);
            }
#pragma unroll
            for (int bj = 0; bj < 2; bj++) {
                int row = wn + bj * 16 + (mt & 1) * 8 + ri;
                ldsm_x4(bH[bj], &Bs[cur][row][colOff]);
            }
#pragma unroll
            for (int mi = 0; mi < 4; mi++)
#pragma unroll
                for (int nj = 0; nj < 4; nj++) {
                    int bj = nj >> 1, s = nj & 1;
                    mma_bf16(acc[mi][nj], aH[mi][0], aH[mi][1], aH[mi][2], aH[mi][3],
                             bH[bj][s], bH[bj][s + 2]);
                }
        }
        __syncthreads();
    }
#undef LOAD_AB
#undef STORE_AB

    // epilogue: scale each row by dinv[row], store bf16x2
    int g = lane >> 2, t = lane & 3;
#pragma unroll
    for (int mi = 0; mi < 4; mi++) {
        int row0 = bRow + wm + mi * 16 + g;
        float d0 = (row0 < M) ? __ldg(&dinv[row0]) : 0.f;
        float d1 = (row0 + 8 < M) ? __ldg(&dinv[row0 + 8]) : 0.f;
#pragma unroll
        for (int nj = 0; nj < 4; nj++) {
            int colp = (bCol + wn + nj * 8 + t * 2) >> 1;
            if (row0 < M)
                C[(size_t)row0 * Hd2 + colp] =
                    __floats2bfloat162_rn(acc[mi][nj][0] * d0, acc[mi][nj][1] * d0);
            if (row0 + 8 < M)
                C[(size_t)(row0 + 8) * Hd2 + colp] =
                    __floats2bfloat162_rn(acc[mi][nj][2] * d1, acc[mi][nj][3] * d1);
        }
    }
}

// ---------------- small fp32 GEMM (single) ----------------
__global__ __launch_bounds__(256) void sgemm64_kernel(const float* __restrict__ A, int lda,
                                                      const float* __restrict__ Bm,
                                                      const float* __restrict__ bias,
                                                      float* __restrict__ C, int ldc,
                                                      int M, int N, int K, int doRelu) {
    const int BM = 64, BN = 64, BK = 16, TM = 4, TN = 4;
    __shared__ float As[BK][BM];
    __shared__ float Bs[BK][BN];
    const int tid = threadIdx.x;
    const int bRow = blockIdx.y * BM;
    const int bCol = blockIdx.x * BN;
    const int tx = tid % 16;
    const int ty = tid / 16;

    float acc[TM][TN];
#pragma unroll
    for (int i = 0; i < TM; i++)
#pragma unroll
        for (int j = 0; j < TN; j++) acc[i][j] = 0.0f;

    for (int k0 = 0; k0 < K; k0 += BK) {
        {
            int i = tid;
            int r = i >> 2;
            int c4 = (i & 3) << 2;
            int grow = bRow + r;
            float4 v = make_float4(0.f, 0.f, 0.f, 0.f);
            if (grow < M) v = *reinterpret_cast<const float4*>(&A[(size_t)grow * lda + k0 + c4]);
            As[c4 + 0][r] = v.x; As[c4 + 1][r] = v.y; As[c4 + 2][r] = v.z; As[c4 + 3][r] = v.w;
        }
        {
            int i = tid;
            int r = i >> 4;
            int c = (i & 15) << 2;
            float4 v = *reinterpret_cast<const float4*>(&Bm[(size_t)(k0 + r) * N + bCol + c]);
            *reinterpret_cast<float4*>(&Bs[r][c]) = v;
        }
        __syncthreads();

        float ar[TM], br[TN];
#pragma unroll
        for (int kk = 0; kk < BK; kk++) {
#pragma unroll
            for (int i = 0; i < TM; i++) ar[i] = As[kk][ty * TM + i];
#pragma unroll
            for (int j = 0; j < TN; j++) br[j] = Bs[kk][tx * TN + j];
#pragma unroll
            for (int i = 0; i < TM; i++)
#pragma unroll
                for (int j = 0; j < TN; j++) acc[i][j] += ar[i] * br[j];
        }
        __syncthreads();
    }

#pragma unroll
    for (int i = 0; i < TM; i++) {
        int grow = bRow + ty * TM + i;
        if (grow >= M) continue;
#pragma unroll
        for (int j = 0; j < TN; j++) {
            int gcol = bCol + tx * TN + j;
            float v = acc[i][j];
            if (bias) v += bias[gcol];
            if (doRelu) v = fmaxf(v, 0.0f);
            C[(size_t)grow * ldc + gcol] = v;
        }
    }
}

// ---------------- small fp32 GEMM, 3-way z-select (generic M/K) ----------------
__global__ __launch_bounds__(256) void sgemm64_3_kernel(
    const float* A0, const float* A1, const float* A2, int lda,
    const float* B0, const float* B1, const float* B2,
    float* C0, float* C1, float* C2, int ldc, int M, int N, int K)
{
    const float* A = (blockIdx.z == 0) ? A0 : (blockIdx.z == 1) ? A1 : A2;
    const float* Bm = (blockIdx.z == 0) ? B0 : (blockIdx.z == 1) ? B1 : B2;
    float* C = (blockIdx.z == 0) ? C0 : (blockIdx.z == 1) ? C1 : C2;

    const int BM = 64, BN = 64, BK = 16, TM = 4, TN = 4;
    __shared__ float As[BK][BM];
    __shared__ float Bs[BK][BN];
    const int tid = threadIdx.x;
    const int bRow = blockIdx.y * BM;
    const int bCol = blockIdx.x * BN;
    const int tx = tid % 16;
    const int ty = tid / 16;

    float acc[TM][TN];
#pragma unroll
    for (int i = 0; i < TM; i++)
#pragma unroll
        for (int j = 0; j < TN; j++) acc[i][j] = 0.0f;

    for (int k0 = 0; k0 < K; k0 += BK) {
        {
            int i = tid;
            int r = i >> 2;
            int c4 = (i & 3) << 2;
            int grow = bRow + r;
            float4 v = make_float4(0.f, 0.f, 0.f, 0.f);
            if (grow < M) v = *reinterpret_cast<const float4*>(&A[(size_t)grow * lda + k0 + c4]);
            As[c4 + 0][r] = v.x; As[c4 + 1][r] = v.y; As[c4 + 2][r] = v.z; As[c4 + 3][r] = v.w;
        }
        {
            int i = tid;
            int r = i >> 4;
            int c = (i & 15) << 2;
            float4 v = *reinterpret_cast<const float4*>(&Bm[(size_t)(k0 + r) * N + bCol + c]);
            *reinterpret_cast<float4*>(&Bs[r][c]) = v;
        }
        __syncthreads();

        float ar[TM], br[TN];
#pragma unroll
        for (int kk = 0; kk < BK; kk++) {
#pragma unroll
            for (int i = 0; i < TM; i++) ar[i] = As[kk][ty * TM + i];
#pragma unroll
            for (int j = 0; j < TN; j++) br[j] = Bs[kk][tx * TN + j];
#pragma unroll
            for (int i = 0; i < TM; i++)
#pragma unroll
                for (int j = 0; j < TN; j++) acc[i][j] += ar[i] * br[j];
        }
        __syncthreads();
    }

#pragma unroll
    for (int i = 0; i < TM; i++) {
        int grow = bRow + ty * TM + i;
        if (grow >= M) continue;
#pragma unroll
        for (int j = 0; j < TN; j++) {
            int gcol = bCol + tx * TN + j;
            C[(size_t)grow * ldc + gcol] = acc[i][j];
        }
    }
}

// ---------------- small fp32 GEMM, 4-way z-select (M=Bsz; per-z K/lda; N=Hd) ----------------
__global__ __launch_bounds__(256) void sgemm64_4_kernel(
    const float* A0, const float* A1, const float* A2, const float* A3,
    const float* B0, const float* B1, const float* B2, const float* B3,
    float* C0, float* C1, float* C2, float* C3, int ldc)
{
    int z = blockIdx.z;
    const float* A = (z == 0) ? A0 : (z == 1) ? A1 : (z == 2) ? A2 : A3;
    const float* Bm = (z == 0) ? B0 : (z == 1) ? B1 : (z == 2) ? B2 : B3;
    float* C = (z == 0) ? C0 : (z == 1) ? C1 : (z == 2) ? C2 : C3;
    const int K = (z == 3) ? Hd : Dd;
    const int lda = K;
    const int M = Bsz;
    const int N = Hd;

    const int BM = 64, BN = 64, BK = 16, TM = 4, TN = 4;
    __shared__ float As[BK][BM];
    __shared__ float Bs[BK][BN];
    const int tid = threadIdx.x;
    const int bRow = blockIdx.y * BM;
    const int bCol = blockIdx.x * BN;
    const int tx = tid % 16;
    const int ty = tid / 16;

    float acc[TM][TN];
#pragma unroll
    for (int i = 0; i < TM; i++)
#pragma unroll
        for (int j = 0; j < TN; j++) acc[i][j] = 0.0f;

    for (int k0 = 0; k0 < K; k0 += BK) {
        {
            int i = tid;
            int r = i >> 2;
            int c4 = (i & 3) << 2;
            int grow = bRow + r;
            float4 v = make_float4(0.f, 0.f, 0.f, 0.f);
            if (grow < M) v = *reinterpret_cast<const float4*>(&A[(size_t)grow * lda + k0 + c4]);
            As[c4 + 0][r] = v.x; As[c4 + 1][r] = v.y; As[c4 + 2][r] = v.z; As[c4 + 3][r] = v.w;
        }
        {
            int i = tid;
            int r = i >> 4;
            int c = (i & 15) << 2;
            float4 v = *reinterpret_cast<const float4*>(&Bm[(size_t)(k0 + r) * N + bCol + c]);
            *reinterpret_cast<float4*>(&Bs[r][c]) = v;
        }
        __syncthreads();

        float ar[TM], br[TN];
#pragma unroll
        for (int kk = 0; kk < BK; kk++) {
#pragma unroll
            for (int i = 0; i < TM; i++) ar[i] = As[kk][ty * TM + i];
#pragma unroll
            for (int j = 0; j < TN; j++) br[j] = Bs[kk][tx * TN + j];
#pragma unroll
            for (int i = 0; i < TM; i++)
#pragma unroll
                for (int j = 0; j < TN; j++) acc[i][j] += ar[i] * br[j];
        }
        __syncthreads();
    }

#pragma unroll
    for (int i = 0; i < TM; i++) {
        int grow = bRow + ty * TM + i;
        if (grow >= M) continue;
#pragma unroll
        for (int j = 0; j < TN; j++) {
            int gcol = bCol + tx * TN + j;
            C[(size_t)grow * ldc + gcol] = acc[i][j];
        }
    }
}

// ---------------- head ----------------
__global__ void head_kernel(const float* __restrict__ h, const float* __restrict__ W2,
                            const float* __restrict__ b2, const int* __restrict__ label,
                            float* __restrict__ out, int out_size) {
    __shared__ float preds[Bsz][2];
    int tid = threadIdx.x;
    if (tid < Bsz * 2) {
        int r = tid >> 1, c = tid & 1;
        float s = b2[c];
        for (int k = 0; k < Hd; k++) s += h[r * Hd + k] * W2[k * 2 + c];
        preds[r][c] = s;
    }
    __syncthreads();
    if (tid < Bsz * 2 && tid < out_size) out[tid] = preds[tid >> 1][tid & 1];
    if (tid == 0 && out_size >= Bsz * 2 + 1) {
        float loss = 0.0f;
        for (int r = 0; r < Bsz; r++) {
            float a = preds[r][0], b = preds[r][1];
            float m = fmaxf(a, b);
            float lse = m + logf(expf(a - m) + expf(b - m));
            int y = label[r];
            loss += lse - (y ? b : a);
        }
        out[Bsz * 2] = loss / (float)Bsz;
    }
}

// ---------------- launch (single stream) ----------------
extern "C" void kernel_launch(void* const* d_in, const int* in_sizes, int n_in,
                              void* d_out, int out_size) {
    const float* content  = (const float*)d_in[0];
    const float* video    = (const float*)d_in[1];
    const float* image    = (const float*)d_in[2];
    const float* repost_x = (const float*)d_in[3];
    const float* comment_x= (const float*)d_in[4];
    const float* W_text   = (const float*)d_in[5];
    const float* W_video  = (const float*)d_in[6];
    const float* W_image  = (const float*)d_in[7];
    const float* Wr1      = (const float*)d_in[8];
    const float* Wr2      = (const float*)d_in[9];
    const float* Wc1      = (const float*)d_in[10];
    const float* Wc2      = (const float*)d_in[11];
    const float* W1       = (const float*)d_in[12];
    const float* b1       = (const float*)d_in[13];
    const float* W2       = (const float*)d_in[14];
    const float* b2       = (const float*)d_in[15];
    const int* rei        = (const int*)d_in[16];
    const int* rbatch     = (const int*)d_in[17];
    const int* cei        = (const int*)d_in[18];
    const int* cbatch     = (const int*)d_in[19];
    const int* cgb        = (const int*)d_in[20];
    const int* label      = (const int*)d_in[21];
    float* out            = (float*)d_out;

    __nv_bfloat162 *pXWr, *pP1r, *pXWc, *pP1c;
    float *pDr, *pDc, *pWfr, *pWfc;
    float *pPoolR, *pPoolG, *pGraphs, *pReps, *pHmid;
    __nv_bfloat16 *pWtHiR, *pWtHiC;
    int *pCntR, *pCntC, *pRoR, *pRoC, *pBsum, *pEsR, *pEsC;
    cudaGetSymbolAddress((void**)&pXWr, g_XWr);
    cudaGetSymbolAddress((void**)&pP1r, g_P1r);
    cudaGetSymbolAddress((void**)&pXWc, g_XWc);
    cudaGetSymbolAddress((void**)&pP1c, g_P1c);
    cudaGetSymbolAddress((void**)&pDr, g_dinv_r);
    cudaGetSymbolAddress((void**)&pDc, g_dinv_c);
    cudaGetSymbolAddress((void**)&pWfr, g_Wf_r);
    cudaGetSymbolAddress((void**)&pWfc, g_Wf_c);
    cudaGetSymbolAddress((void**)&pWtHiR, g_WtHiR);
    cudaGetSymbolAddress((void**)&pWtHiC, g_WtHiC);
    cudaGetSymbolAddress((void**)&pPoolR, g_pooled_r);
    cudaGetSymbolAddress((void**)&pPoolG, g_pooledG);
    cudaGetSymbolAddress((void**)&pGraphs, g_graphs);
    cudaGetSymbolAddress((void**)&pReps, g_reps);
    cudaGetSymbolAddress((void**)&pHmid, g_hmid);
    cudaGetSymbolAddress((void**)&pCntR, g_cnt_r);
    cudaGetSymbolAddress((void**)&pCntC, g_cnt_c);
    cudaGetSymbolAddress((void**)&pRoR, g_rowoff_r);
    cudaGetSymbolAddress((void**)&pRoC, g_rowoff_c);
    cudaGetSymbolAddress((void**)&pEsR, g_es_r);
    cudaGetSymbolAddress((void**)&pEsC, g_es_c);
    cudaGetSymbolAddress((void**)&pBsum, g_bsum2);

    const int* r_src = rei;            const int* r_dst = rei + ERn;
    const int* c_src = cei;            const int* c_dst = cei + ECn;

    const int NB = (NRn + 255) / 256;  // 391

    // ---- degrees first (dinv feeds the GEMM epilogue) ----
    cudaMemsetAsync(pCntR, 0, NRn * sizeof(int));
    cudaMemsetAsync(pCntC, 0, NCn * sizeof(int));
    count2_kernel<<<(ERn + 255) / 256, 256>>>(r_dst, c_dst, pCntR, pCntC);
    dinv2_kernel<<<NB, 256>>>(pCntR, pCntC, pDr, pDc);

    // ---- weight prep (M=Dd, K=Hd — via generic 3-way kernel) + dual TC GEMM ----
    sgemm64_3_kernel<<<dim3(Hd / 64, Dd / 64, 2), 256>>>(
        W_text, W_text, W_text, Hd, Wr1, Wc1, Wc1, pWfr, pWfc, pWfc, Hd, Dd, Hd, Hd);
    convtrans2_kernel<<<dim3((Dd * Hd + 255) / 256, 2), 256>>>(pWfr, pWtHiR, pWfc, pWtHiC);
    gemm_bf16_kernel<<<dim3(2, (NRn + 127) / 128, 2), 256>>>(
        repost_x, pWtHiR, pXWr, pDr, comment_x, pWtHiC, pXWc, pDc, NRn);

    // ---- finish CSR (scans + scatter; weightless payload) ----
    scan_blocksum2_kernel<<<dim3(NB, 2), 256>>>(pCntR, pCntC, pBsum, NRn);
    scan_bsum2_kernel<<<dim3(1, 2), 512>>>(pBsum, pRoR, pRoC, NB, NRn);
    scan_final2_kernel<<<dim3(NB, 2), 256>>>(pCntR, pCntC, pBsum, pRoR, pRoC, NRn);
    cudaMemsetAsync(pCntR, 0, NRn * sizeof(int));
    cudaMemsetAsync(pCntC, 0, NCn * sizeof(int));
    scatter2_kernel<<<dim3((ERn + 255) / 256, 2), 256>>>(
        r_src, r_dst, pRoR, pCntR, pEsR,
        c_src, c_dst, pRoC, pCntC, pEsC);

    // ---- layer-1 gather (both graphs, 1 node/block) ----
    gather1_kernel<<<NRn + NCn, 128>>>(pXWr, pP1r, pRoR, pEsR, pDr,
                                       pXWc, pP1c, pRoC, pEsC, pDc);

    // ---- layer-2 + pooling (1 node/block) ----
    cudaMemsetAsync(pPoolR, 0, (size_t)Bsz * Hd * sizeof(float));
    cudaMemsetAsync(pPoolG, 0, (size_t)Gn * Hd * sizeof(float));
    gather2_pool_kernel<<<NRn + NCn, 128>>>(pP1r, pRoR, pEsR, pDr, rbatch, pPoolR,
                                            pP1c, pRoC, pEsC, pDc, cbatch, pPoolG);
    // one launch divides both pools in place
    pool_div2_kernel<<<Gn + Bsz, Hd>>>(pPoolR, rbatch, pPoolG, cbatch);

    // graphs_reps = pooledG @ Wc2 ; fused second-level pool -> reps[:,2H:3H]
    sgemm64_kernel<<<dim3(Hd / 64, Gn / 64), 256>>>(pPoolG, Hd, Wc2, nullptr, pGraphs, Hd, Gn, Hd, Hd, 0);
    pool_graphs_kernel<<<Bsz, Hd>>>(pGraphs, cgb, pReps + 2 * Hd, 5 * Hd);

    // reps: content/video/image/repost in ONE 4-way launch (M=Bsz; K per z)
    sgemm64_4_kernel<<<dim3(Hd / 64, 1, 4), 256>>>(
        content, video, image, pPoolR,
        W_text, W_video, W_image, Wr2,
        pReps + 0 * Hd, pReps + 3 * Hd, pReps + 4 * Hd, pReps + 1 * Hd, 5 * Hd);

    // MLP head
    sgemm64_kernel<<<dim3(Hd / 64, 1), 256>>>(pReps, 5 * Hd, W1, b1, pHmid, Hd, Bsz, Hd, 5 * Hd, 1);
    head_kernel<<<1, 128>>>(pHmid, W2, b2, label, out, out_size);
}